// round 10
// baseline (speedup 1.0000x reference)
#include <cuda_runtime.h>
#include <cuda_bf16.h>
#include <math.h>
#include <cstdint>

#define NN 100000
#define EE 1000000

// ---------------- device scratch (zero-initialized at load; k_clean restores) ----------------
__device__ int    d_cnt[NN];
__device__ int    d_off[NN + 1];
__device__ int    d_cur[NN];
__device__ int    d_scan_tix;
__device__ unsigned long long d_scan_state[128];
__device__ int4   d_adj[EE];                    // {ssrc, eid, pid, 0}
__device__ __nv_bfloat16 d_efb [(size_t)EE * 64];   // bf16 copy of efeats (128MB ~ L2)
__device__ __nv_bfloat16 d_nfb [(size_t)NN * 64];   // bf16 copy of nfeats
__device__ __nv_bfloat16 d_hagg0[(size_t)NN * 64];
__device__ __nv_bfloat16 d_efp [(size_t)NN * 64];
__device__ __nv_bfloat16 d_efn [(size_t)NN * 64];
__device__ __nv_bfloat16 d_h1p [(size_t)NN * 64];
__device__ __nv_bfloat16 d_h1n [(size_t)NN * 64];
// folded W in tf32, stored in exact mma B-fragment order
__device__ float  d_Wf[2][3 * 8 * 8 * 64];
__device__ float  d_cv[2][64];
__device__ double d_loss;

// ---------------- helpers ----------------
__device__ __forceinline__ float tf32r(float x) {
    uint32_t r; asm("cvt.rna.tf32.f32 %0, %1;" : "=r"(r) : "f"(x));
    return __uint_as_float(r);
}
__device__ __forceinline__ void mma_tf32(float* c, uint32_t a0, uint32_t a1, uint32_t a2, uint32_t a3,
                                         uint32_t b0, uint32_t b1) {
    asm volatile("mma.sync.aligned.m16n8k8.row.col.f32.tf32.tf32.f32 "
                 "{%0,%1,%2,%3}, {%4,%5,%6,%7}, {%8,%9}, {%0,%1,%2,%3};"
                 : "+f"(c[0]), "+f"(c[1]), "+f"(c[2]), "+f"(c[3])
                 : "r"(a0), "r"(a1), "r"(a2), "r"(a3), "r"(b0), "r"(b1));
}
__device__ __forceinline__ uint32_t bf2(float x, float y) {
    uint32_t r; asm("cvt.rn.satfinite.bf16x2.f32 %0, %1, %2;" : "=r"(r) : "f"(y), "f"(x)); return r;
}
__device__ __forceinline__ float2 bf2f(uint32_t v) {
    __nv_bfloat162 h = *reinterpret_cast<__nv_bfloat162*>(&v);
    return __bfloat1622float2(h);
}

// ---------------- CSR build + bf16 conversion (fused; hist atomics overlap streaming) ----------------
__global__ void __launch_bounds__(256) k_histcvt(const int* __restrict__ dst,
                                                 const float* __restrict__ ef,
                                                 const float* __restrict__ nf,
                                                 int E, int n) {
    int i = blockIdx.x * blockDim.x + threadIdx.x;
    int nth = gridDim.x * blockDim.x;
    if (i < E) atomicAdd(&d_cnt[dst[i]], 1);
    int tote = E * 16;                      // uint4 chunks of efeats
    uint2* efo = reinterpret_cast<uint2*>(d_efb);
    for (int t = i; t < tote; t += nth) {
        float4 v = __ldg(reinterpret_cast<const float4*>(ef) + t);
        efo[t] = make_uint2(bf2(v.x, v.y), bf2(v.z, v.w));
    }
    int totn = n * 16;
    uint2* nfo = reinterpret_cast<uint2*>(d_nfb);
    for (int t = i; t < totn; t += nth) {
        float4 v = __ldg(reinterpret_cast<const float4*>(nf) + t);
        nfo[t] = make_uint2(bf2(v.x, v.y), bf2(v.z, v.w));
    }
}

__global__ void k_scan(int n, int E, int nb) {
    __shared__ int ws[32];
    __shared__ int s_bid;
    __shared__ int s_pref;
    if (threadIdx.x == 0) s_bid = atomicAdd(&d_scan_tix, 1);
    __syncthreads();
    int bid = s_bid;
    int i = bid * 1024 + threadIdx.x;
    int lane = threadIdx.x & 31, wid = threadIdx.x >> 5;
    int v = (i < n) ? d_cnt[i] : 0;
    int x = v;
    #pragma unroll
    for (int o = 1; o < 32; o <<= 1) { int y = __shfl_up_sync(~0u, x, o); if (lane >= o) x += y; }
    if (lane == 31) ws[wid] = x;
    __syncthreads();
    if (wid == 0) {
        int w = ws[lane];
        #pragma unroll
        for (int o = 1; o < 32; o <<= 1) { int y = __shfl_up_sync(~0u, w, o); if (lane >= o) w += y; }
        ws[lane] = w;
    }
    __syncthreads();
    int incl = x + (wid > 0 ? ws[wid - 1] : 0);
    int total = ws[31];
    if (threadIdx.x == 0) {
        if (bid == 0) {
            atomicExch(&d_scan_state[0], (2ULL << 32) | (unsigned)total);
            s_pref = 0;
        } else {
            atomicExch(&d_scan_state[bid], (1ULL << 32) | (unsigned)total);
            int pref = 0;
            for (int j = bid - 1; j >= 0; --j) {
                unsigned long long st;
                do { st = atomicAdd(&d_scan_state[j], 0ULL); } while (!(st >> 32));
                pref += (int)(unsigned)st;
                if ((st >> 32) == 2ULL) break;
            }
            atomicExch(&d_scan_state[bid], (2ULL << 32) | (unsigned)(pref + total));
            s_pref = pref;
        }
    }
    __syncthreads();
    int pref = s_pref;
    if (i < n) d_off[i] = pref + incl - v;
    if (bid == nb - 1 && threadIdx.x == 0) d_off[n] = E;
}

__global__ void k_scatter(const int* __restrict__ src, const int* __restrict__ dst,
                          const int* __restrict__ perm, int E) {
    int e = blockIdx.x * blockDim.x + threadIdx.x;
    if (e < E) {
        int d = dst[e];
        int p = d_off[d] + atomicAdd(&d_cur[d], 1);
        d_adj[p] = make_int4(src[e], e, perm[e], 0);
    }
}

// ---------------- fused first-stage aggregation (bf16 tables, 128B rows) ----------------
// Lane owns bf16x2 column [lane]; unroll-by-4 -> 12 independent table loads in flight.
__global__ void __launch_bounds__(256) k_agg3(int n) {
    int gw = (blockIdx.x * blockDim.x + threadIdx.x) >> 5;
    int lane = threadIdx.x & 31;
    if (gw >= n) return;
    int beg = d_off[gw], end = d_off[gw + 1];
    const uint32_t* nfb = reinterpret_cast<const uint32_t*>(d_nfb);
    const uint32_t* efb = reinterpret_cast<const uint32_t*>(d_efb);
    float2 ah = make_float2(0.f, 0.f), ap = ah, an = ah;
    int k = beg;
    for (; k + 4 <= end; k += 4) {
        int4 a0 = __ldg(&d_adj[k]);
        int4 a1 = __ldg(&d_adj[k + 1]);
        int4 a2 = __ldg(&d_adj[k + 2]);
        int4 a3 = __ldg(&d_adj[k + 3]);
        uint32_t h0 = __ldg(nfb + ((size_t)a0.x * 32 + lane));
        uint32_t p0 = __ldg(efb + ((size_t)a0.y * 32 + lane));
        uint32_t q0 = __ldg(efb + ((size_t)a0.z * 32 + lane));
        uint32_t h1 = __ldg(nfb + ((size_t)a1.x * 32 + lane));
        uint32_t p1 = __ldg(efb + ((size_t)a1.y * 32 + lane));
        uint32_t q1 = __ldg(efb + ((size_t)a1.z * 32 + lane));
        uint32_t h2 = __ldg(nfb + ((size_t)a2.x * 32 + lane));
        uint32_t p2 = __ldg(efb + ((size_t)a2.y * 32 + lane));
        uint32_t q2 = __ldg(efb + ((size_t)a2.z * 32 + lane));
        uint32_t h3 = __ldg(nfb + ((size_t)a3.x * 32 + lane));
        uint32_t p3 = __ldg(efb + ((size_t)a3.y * 32 + lane));
        uint32_t q3 = __ldg(efb + ((size_t)a3.z * 32 + lane));
        float2 t;
        t = bf2f(h0); ah.x += t.x; ah.y += t.y;
        t = bf2f(h1); ah.x += t.x; ah.y += t.y;
        t = bf2f(h2); ah.x += t.x; ah.y += t.y;
        t = bf2f(h3); ah.x += t.x; ah.y += t.y;
        t = bf2f(p0); ap.x += t.x; ap.y += t.y;
        t = bf2f(p1); ap.x += t.x; ap.y += t.y;
        t = bf2f(p2); ap.x += t.x; ap.y += t.y;
        t = bf2f(p3); ap.x += t.x; ap.y += t.y;
        t = bf2f(q0); an.x += t.x; an.y += t.y;
        t = bf2f(q1); an.x += t.x; an.y += t.y;
        t = bf2f(q2); an.x += t.x; an.y += t.y;
        t = bf2f(q3); an.x += t.x; an.y += t.y;
    }
    for (; k < end; ++k) {
        int4 a = __ldg(&d_adj[k]);
        float2 t;
        t = bf2f(__ldg(nfb + ((size_t)a.x * 32 + lane))); ah.x += t.x; ah.y += t.y;
        t = bf2f(__ldg(efb + ((size_t)a.y * 32 + lane))); ap.x += t.x; ap.y += t.y;
        t = bf2f(__ldg(efb + ((size_t)a.z * 32 + lane))); an.x += t.x; an.y += t.y;
    }
    float inv = 1.f / fmaxf((float)(end - beg), 1.f);
    reinterpret_cast<uint32_t*>(d_hagg0)[(size_t)gw * 32 + lane] = bf2(ah.x * inv, ah.y * inv);
    reinterpret_cast<uint32_t*>(d_efp)  [(size_t)gw * 32 + lane] = bf2(ap.x * inv, ap.y * inv);
    reinterpret_cast<uint32_t*>(d_efn)  [(size_t)gw * 32 + lane] = bf2(an.x * inv, an.y * inv);
}

// ---------------- fold Wmsg into Wapply -> tf32 B-fragment layout ----------------
__global__ void k_fold2(const float* __restrict__ Wm0, const float* __restrict__ bm0,
                        const float* __restrict__ Wa0,
                        const float* __restrict__ Wm1, const float* __restrict__ bm1,
                        const float* __restrict__ Wa1) {
    int layer = blockIdx.x;
    const float* Wmsg = layer ? Wm1 : Wm0;
    const float* bmsg = layer ? bm1 : bm0;
    const float* Wap  = layer ? Wa1 : Wa0;
    __shared__ float Wn[64][64];
    __shared__ float bm[64];
    int tid = threadIdx.x;
    for (int idx = tid; idx < 64 * 64; idx += 256) {
        int j = idx >> 6, t = idx & 63;
        Wn[t][j] = Wap[j * 128 + 64 + t];
    }
    if (tid < 64) bm[tid] = bmsg[tid];
    __syncthreads();
    for (int idx = tid; idx < 192 * 64; idx += 256) {
        int k = idx >> 6, j = idx & 63;
        float r;
        if (k < 64) {
            r = Wap[j * 128 + k];
        } else {
            int col = k - 64;
            float a = 0.f;
            #pragma unroll
            for (int t = 0; t < 64; ++t) a += Wmsg[t * 128 + col] * Wn[t][j];
            r = a;
        }
        int panel = k >> 6, kk = k & 63;
        int s = kk >> 3, krem = kk & 7;
        int slot = krem >> 2, kq = krem & 3;
        int t = ((j & 7) << 2) | kq;
        int nb = j >> 3;
        int o = ((panel * 8 + s) * 8 + nb) * 64 + t * 2 + slot;
        d_Wf[layer][o] = tf32r(r);
    }
    for (int j = tid; j < 64; j += 256) {
        float a = 0.f;
        #pragma unroll
        for (int t = 0; t < 64; ++t) a += bm[t] * Wn[t][j];
        d_cv[layer][j] = a;
    }
}

// ---------------- mma GEMM building blocks ----------------
#define XST 68
#define SM_X 0
#define SM_W (128 * XST)
#define SM_B (SM_W + 64 * 64)
#define SM_C (SM_B + 64)
#define SM_TOTF (SM_C + 64)
#define GEMM_SMEM (SM_TOTF * 4)
// l1 adds a 128x32-u32 aggregate buffer
#define L1_AG SM_TOTF
#define L1_SMEM ((SM_TOTF + 4096) * 4)

__device__ __forceinline__ void stage_bf16(float* __restrict__ Xs, const __nv_bfloat16* __restrict__ S,
                                           int node0, int n, int tid) {
    #pragma unroll
    for (int it = 0; it < 4; ++it) {
        int t = tid + it * 256;
        int r = t >> 3, u4 = t & 7;
        int nd = node0 + r;
        uint4 v = make_uint4(0u, 0u, 0u, 0u);
        if (nd < n) v = __ldg(reinterpret_cast<const uint4*>(S) + (size_t)nd * 8 + u4);
        float2 f0 = bf2f(v.x), f1 = bf2f(v.y), f2 = bf2f(v.z), f3 = bf2f(v.w);
        *reinterpret_cast<float4*>(Xs + r * XST + u4 * 8)     = make_float4(f0.x, f0.y, f1.x, f1.y);
        *reinterpret_cast<float4*>(Xs + r * XST + u4 * 8 + 4) = make_float4(f2.x, f2.y, f3.x, f3.y);
    }
}
__device__ __forceinline__ void stage_sm(float* __restrict__ Xs, const uint32_t* __restrict__ B, int tid) {
    #pragma unroll
    for (int it = 0; it < 4; ++it) {
        int t = tid + it * 256;
        int r = t >> 3, u4 = t & 7;
        uint4 v = *reinterpret_cast<const uint4*>(B + r * 32 + u4 * 4);
        float2 f0 = bf2f(v.x), f1 = bf2f(v.y), f2 = bf2f(v.z), f3 = bf2f(v.w);
        *reinterpret_cast<float4*>(Xs + r * XST + u4 * 8)     = make_float4(f0.x, f0.y, f1.x, f1.y);
        *reinterpret_cast<float4*>(Xs + r * XST + u4 * 8 + 4) = make_float4(f2.x, f2.y, f3.x, f3.y);
    }
}
__device__ __forceinline__ void stage_w(float* __restrict__ Wp, const float* __restrict__ Wg, int tid) {
    #pragma unroll
    for (int it = 0; it < 4; ++it) {
        int t = tid + it * 256;
        reinterpret_cast<float4*>(Wp)[t] = __ldg(reinterpret_cast<const float4*>(Wg) + t);
    }
}
__device__ __forceinline__ void mma_phase(const float* __restrict__ Xs, const float* __restrict__ Wp,
                                          float* acc, int r0w, int lane) {
    int ar = r0w + (lane >> 2);
    #pragma unroll
    for (int s = 0; s < 8; ++s) {
        int ac = s * 8 + (lane & 3);
        uint32_t a0 = __float_as_uint(Xs[ar * XST + ac]);
        uint32_t a1 = __float_as_uint(Xs[(ar + 8) * XST + ac]);
        uint32_t a2 = __float_as_uint(Xs[ar * XST + ac + 4]);
        uint32_t a3 = __float_as_uint(Xs[(ar + 8) * XST + ac + 4]);
        #pragma unroll
        for (int nb = 0; nb < 8; ++nb) {
            float2 b = *reinterpret_cast<const float2*>(Wp + (s * 8 + nb) * 64 + lane * 2);
            mma_tf32(acc + nb * 4, a0, a1, a2, a3, __float_as_uint(b.x), __float_as_uint(b.y));
        }
    }
}

__device__ __forceinline__ float indf(int nd, int n) {
    return (nd < n && d_off[nd + 1] > d_off[nd]) ? 1.f : 0.f;
}

__device__ __forceinline__ void epi0(const float* acc, const float* __restrict__ sb,
                                     const float* __restrict__ sc, __nv_bfloat16* __restrict__ out,
                                     int node0, int r0w, int lane, int n) {
    int rA = node0 + r0w + (lane >> 2);
    int rB = rA + 8;
    float indA = indf(rA, n), indB = indf(rB, n);
    uint32_t* o32 = reinterpret_cast<uint32_t*>(out);
    #pragma unroll
    for (int nb = 0; nb < 8; ++nb) {
        int cc = nb * 8 + (lane & 3) * 2;
        float xA0 = fmaxf(acc[nb*4+0] + sb[cc]   + indA * sc[cc],   0.f);
        float xA1 = fmaxf(acc[nb*4+1] + sb[cc+1] + indA * sc[cc+1], 0.f);
        float xB0 = fmaxf(acc[nb*4+2] + sb[cc]   + indB * sc[cc],   0.f);
        float xB1 = fmaxf(acc[nb*4+3] + sb[cc+1] + indB * sc[cc+1], 0.f);
        if (rA < n) o32[(size_t)rA * 32 + (cc >> 1)] = bf2(xA0, xA1);
        if (rB < n) o32[(size_t)rB * 32 + (cc >> 1)] = bf2(xB0, xB1);
    }
}

// ---------------- layer 0 ----------------
__global__ void __launch_bounds__(256) k_l0(const float* __restrict__ bap, int n)
{
    extern __shared__ float sm[];
    float* Xs = sm + SM_X;
    float* Wp = sm + SM_W;
    float* sb = sm + SM_B;
    float* sc = sm + SM_C;
    int tid = threadIdx.x, wid = tid >> 5, lane = tid & 31;
    int node0 = blockIdx.x * 128;
    int r0w = wid * 16;
    if (tid < 64) { sb[tid] = bap[tid]; sc[tid] = d_cv[0][tid]; }

    float acc[32], accB[32];
    #pragma unroll
    for (int i = 0; i < 32; ++i) acc[i] = 0.f;

    stage_bf16(Xs, d_nfb, node0, n, tid);
    stage_w(Wp, d_Wf[0], tid);
    __syncthreads();
    mma_phase(Xs, Wp, acc, r0w, lane);
    __syncthreads();

    stage_bf16(Xs, d_hagg0, node0, n, tid);
    stage_w(Wp, d_Wf[0] + 4096, tid);
    __syncthreads();
    mma_phase(Xs, Wp, acc, r0w, lane);
    __syncthreads();
    #pragma unroll
    for (int i = 0; i < 32; ++i) accB[i] = acc[i];

    stage_bf16(Xs, d_efp, node0, n, tid);
    stage_w(Wp, d_Wf[0] + 8192, tid);
    __syncthreads();
    mma_phase(Xs, Wp, acc, r0w, lane);
    epi0(acc, sb, sc, d_h1p, node0, r0w, lane, n);
    __syncthreads();

    stage_bf16(Xs, d_efn, node0, n, tid);
    __syncthreads();
    #pragma unroll
    for (int i = 0; i < 32; ++i) acc[i] = accB[i];
    mma_phase(Xs, Wp, acc, r0w, lane);
    epi0(acc, sb, sc, d_h1n, node0, r0w, lane, n);
}

// ---------------- layer 1: fused h-aggregation + 3-phase MMA + BCE ----------------
__global__ void __launch_bounds__(256) k_l1(const float* __restrict__ bap, int n)
{
    extern __shared__ float sm[];
    float* Xs = sm + SM_X;
    float* Wp = sm + SM_W;
    float* sb = sm + SM_B;
    float* sc = sm + SM_C;
    uint32_t* Bh = reinterpret_cast<uint32_t*>(sm + L1_AG);
    __shared__ float wred[8];
    int tid = threadIdx.x, wid = tid >> 5, lane = tid & 31;
    int node0 = blockIdx.x * 128;
    int r0w = wid * 16;
    int view = blockIdx.y;
    if (tid < 64) { sb[tid] = bap[tid]; sc[tid] = d_cv[1][tid]; }

    const __nv_bfloat16* S0 = view ? d_h1n : d_h1p;
    const __nv_bfloat16* S2 = view ? d_efn : d_efp;
    const uint32_t* ft = reinterpret_cast<const uint32_t*>(S0);
    const int* adjs = reinterpret_cast<const int*>(d_adj);

    // stage A: aggregate S0 over in-edges -> Bh (bf16x2 per lane per node)
    #pragma unroll 1
    for (int rr = 0; rr < 16; ++rr) {
        int r = r0w + rr;
        int nd = node0 + r;
        float ax = 0.f, ay = 0.f;
        int beg = 0, end = 0;
        if (nd < n) { beg = d_off[nd]; end = d_off[nd + 1]; }
        int k = beg;
        for (; k + 4 <= end; k += 4) {
            int s0 = __ldg(adjs + 4 * k);
            int s1 = __ldg(adjs + 4 * (k + 1));
            int s2 = __ldg(adjs + 4 * (k + 2));
            int s3 = __ldg(adjs + 4 * (k + 3));
            uint32_t v0 = __ldg(ft + ((size_t)s0 * 32 + lane));
            uint32_t v1 = __ldg(ft + ((size_t)s1 * 32 + lane));
            uint32_t v2 = __ldg(ft + ((size_t)s2 * 32 + lane));
            uint32_t v3 = __ldg(ft + ((size_t)s3 * 32 + lane));
            float2 t;
            t = bf2f(v0); ax += t.x; ay += t.y;
            t = bf2f(v1); ax += t.x; ay += t.y;
            t = bf2f(v2); ax += t.x; ay += t.y;
            t = bf2f(v3); ax += t.x; ay += t.y;
        }
        for (; k < end; ++k) {
            int s = __ldg(adjs + 4 * k);
            float2 t = bf2f(__ldg(ft + ((size_t)s * 32 + lane)));
            ax += t.x; ay += t.y;
        }
        float inv = 1.f / fmaxf((float)(end - beg), 1.f);
        Bh[r * 32 + lane] = bf2(ax * inv, ay * inv);
    }

    float acc[32];
    #pragma unroll
    for (int i = 0; i < 32; ++i) acc[i] = 0.f;

    // p0: own h1 rows (gmem)
    stage_bf16(Xs, S0, node0, n, tid);
    stage_w(Wp, d_Wf[1], tid);
    __syncthreads();
    mma_phase(Xs, Wp, acc, r0w, lane);
    __syncthreads();

    // p1: h-aggregate (smem Bh)
    stage_sm(Xs, Bh, tid);
    stage_w(Wp, d_Wf[1] + 4096, tid);
    __syncthreads();
    mma_phase(Xs, Wp, acc, r0w, lane);
    __syncthreads();

    // p2: ef aggregate (gmem)
    stage_bf16(Xs, S2, node0, n, tid);
    stage_w(Wp, d_Wf[1] + 8192, tid);
    __syncthreads();
    mma_phase(Xs, Wp, acc, r0w, lane);

    // BCE epilogue
    int rA = node0 + r0w + (lane >> 2);
    int rB = rA + 8;
    float indA = indf(rA, n), indB = indf(rB, n);
    float lsum = 0.f;
    #pragma unroll
    for (int nb = 0; nb < 8; ++nb) {
        int cc = nb * 8 + (lane & 3) * 2;
        float xA0 = fmaxf(acc[nb*4+0] + sb[cc]   + indA * sc[cc],   0.f);
        float xA1 = fmaxf(acc[nb*4+1] + sb[cc+1] + indA * sc[cc+1], 0.f);
        float xB0 = fmaxf(acc[nb*4+2] + sb[cc]   + indB * sc[cc],   0.f);
        float xB1 = fmaxf(acc[nb*4+3] + sb[cc+1] + indB * sc[cc+1], 0.f);
        if (rA < n) {
            float t0 = log1pf(expf(-xA0)), t1 = log1pf(expf(-xA1));
            lsum += view ? (xA0 + t0 + xA1 + t1) : (t0 + t1);
        }
        if (rB < n) {
            float t0 = log1pf(expf(-xB0)), t1 = log1pf(expf(-xB1));
            lsum += view ? (xB0 + t0 + xB1 + t1) : (t0 + t1);
        }
    }
    #pragma unroll
    for (int o = 16; o; o >>= 1) lsum += __shfl_down_sync(~0u, lsum, o);
    if (lane == 0) wred[wid] = lsum;
    __syncthreads();
    if (tid < 8) {
        float s = wred[tid];
        #pragma unroll
        for (int o = 4; o; o >>= 1) s += __shfl_down_sync(0xffu, s, o);
        if (tid == 0) atomicAdd(&d_loss, (double)s);
    }
}

// ---------------- write result + restore zero-state invariant ----------------
__global__ void k_clean(float* out, double denom, int n) {
    int i = blockIdx.x * blockDim.x + threadIdx.x;
    if (i == 0) {
        out[0] = (float)(d_loss / denom);
        d_loss = 0.0;
        d_scan_tix = 0;
    }
    if (i < 128) d_scan_state[i] = 0ULL;
    if (i < n) { d_cnt[i] = 0; d_cur[i] = 0; }
}

// ---------------- launch ----------------
extern "C" void kernel_launch(void* const* d_in, const int* in_sizes, int n_in,
                              void* d_out, int out_size) {
    const float* nfeats = (const float*)d_in[0];
    const float* efeats = (const float*)d_in[1];
    const int*   src    = (const int*)d_in[2];
    const int*   dst    = (const int*)d_in[3];
    const int*   perm   = (const int*)d_in[4];
    const float* Wm0 = (const float*)d_in[5];
    const float* bm0 = (const float*)d_in[6];
    const float* Wa0 = (const float*)d_in[7];
    const float* ba0 = (const float*)d_in[8];
    const float* Wm1 = (const float*)d_in[9];
    const float* bm1 = (const float*)d_in[10];
    const float* Wa1 = (const float*)d_in[11];
    const float* ba1 = (const float*)d_in[12];

    int n = in_sizes[0] / 64;
    int E = in_sizes[2];
    int nb = (n + 1023) / 1024;

    cudaFuncSetAttribute(k_l0, cudaFuncAttributeMaxDynamicSharedMemorySize, GEMM_SMEM);
    cudaFuncSetAttribute(k_l1, cudaFuncAttributeMaxDynamicSharedMemorySize, L1_SMEM);

    int gw = (n * 32 + 255) / 256;  // one warp per node
    int gl = (n + 127) / 128;       // 128 nodes per tile

    k_histcvt<<<(E + 255) / 256, 256>>>(dst, efeats, nfeats, E, n);  // 1
    k_scan   <<<nb, 1024>>>(n, E, nb);                               // 2
    k_scatter<<<(E + 255) / 256, 256>>>(src, dst, perm, E);          // 3
    k_agg3   <<<gw, 256>>>(n);                                       // 4 <- profiled
    k_fold2  <<<2, 256>>>(Wm0, bm0, Wa0, Wm1, bm1, Wa1);             // 5
    k_l0     <<<gl, 256, GEMM_SMEM>>>(ba0, n);                       // 6
    {
        dim3 grid(gl, 2);
        k_l1 <<<grid, 256, L1_SMEM>>>(ba1, n);                       // 7
    }
    k_clean  <<<(n + 255) / 256, 256>>>((float*)d_out, (double)n * 64.0, n); // 8
}

// round 11
// speedup vs baseline: 1.2112x; 1.2112x over previous
#include <cuda_runtime.h>
#include <cuda_bf16.h>
#include <math.h>
#include <cstdint>

#define NN 100000
#define EE 1000000

// ---------------- device scratch (zero-initialized at load; k_clean restores) ----------------
__device__ int    d_cnt[NN];
__device__ int    d_off[NN + 1];
__device__ int    d_cur[NN];
__device__ int    d_scan_tix;
__device__ unsigned long long d_scan_state[128];
__device__ int4   d_adj[EE];                    // {ssrc, eid, pid, 0}
__device__ __nv_bfloat16 d_efb [(size_t)EE * 64];   // bf16 copy of efeats (~L2-sized)
__device__ __nv_bfloat16 d_nfb [(size_t)NN * 64];   // bf16 copy of nfeats
__device__ __nv_bfloat16 d_hagg0[(size_t)NN * 64];
__device__ __nv_bfloat16 d_efp [(size_t)NN * 64];
__device__ __nv_bfloat16 d_efn [(size_t)NN * 64];
__device__ __nv_bfloat16 d_h1p [(size_t)NN * 64];
__device__ __nv_bfloat16 d_h1n [(size_t)NN * 64];
__device__ __nv_bfloat16 d_hp  [(size_t)NN * 64];
__device__ __nv_bfloat16 d_hn  [(size_t)NN * 64];
// folded W in tf32, stored in exact mma B-fragment order
__device__ float  d_Wf[2][3 * 8 * 8 * 64];
__device__ float  d_cv[2][64];
__device__ double d_loss;

// ---------------- helpers ----------------
__device__ __forceinline__ float tf32r(float x) {
    uint32_t r; asm("cvt.rna.tf32.f32 %0, %1;" : "=r"(r) : "f"(x));
    return __uint_as_float(r);
}
__device__ __forceinline__ void mma_tf32(float* c, uint32_t a0, uint32_t a1, uint32_t a2, uint32_t a3,
                                         uint32_t b0, uint32_t b1) {
    asm volatile("mma.sync.aligned.m16n8k8.row.col.f32.tf32.tf32.f32 "
                 "{%0,%1,%2,%3}, {%4,%5,%6,%7}, {%8,%9}, {%0,%1,%2,%3};"
                 : "+f"(c[0]), "+f"(c[1]), "+f"(c[2]), "+f"(c[3])
                 : "r"(a0), "r"(a1), "r"(a2), "r"(a3), "r"(b0), "r"(b1));
}
__device__ __forceinline__ uint32_t bf2(float x, float y) {
    uint32_t r; asm("cvt.rn.satfinite.bf16x2.f32 %0, %1, %2;" : "=r"(r) : "f"(y), "f"(x)); return r;
}
__device__ __forceinline__ float2 bf2f(uint32_t v) {
    __nv_bfloat162 h = *reinterpret_cast<__nv_bfloat162*>(&v);
    return __bfloat1622float2(h);
}

// ---------------- CSR build + bf16 conversion (fused) ----------------
__global__ void __launch_bounds__(256) k_histcvt(const int* __restrict__ dst,
                                                 const float* __restrict__ ef,
                                                 const float* __restrict__ nf,
                                                 int E, int n) {
    int i = blockIdx.x * blockDim.x + threadIdx.x;
    int nth = gridDim.x * blockDim.x;
    if (i < E) atomicAdd(&d_cnt[dst[i]], 1);
    int tote = E * 16;
    uint2* efo = reinterpret_cast<uint2*>(d_efb);
    for (int t = i; t < tote; t += nth) {
        float4 v = __ldg(reinterpret_cast<const float4*>(ef) + t);
        efo[t] = make_uint2(bf2(v.x, v.y), bf2(v.z, v.w));
    }
    int totn = n * 16;
    uint2* nfo = reinterpret_cast<uint2*>(d_nfb);
    for (int t = i; t < totn; t += nth) {
        float4 v = __ldg(reinterpret_cast<const float4*>(nf) + t);
        nfo[t] = make_uint2(bf2(v.x, v.y), bf2(v.z, v.w));
    }
}

__global__ void k_scan(int n, int E, int nb) {
    __shared__ int ws[32];
    __shared__ int s_bid;
    __shared__ int s_pref;
    if (threadIdx.x == 0) s_bid = atomicAdd(&d_scan_tix, 1);
    __syncthreads();
    int bid = s_bid;
    int i = bid * 1024 + threadIdx.x;
    int lane = threadIdx.x & 31, wid = threadIdx.x >> 5;
    int v = (i < n) ? d_cnt[i] : 0;
    int x = v;
    #pragma unroll
    for (int o = 1; o < 32; o <<= 1) { int y = __shfl_up_sync(~0u, x, o); if (lane >= o) x += y; }
    if (lane == 31) ws[wid] = x;
    __syncthreads();
    if (wid == 0) {
        int w = ws[lane];
        #pragma unroll
        for (int o = 1; o < 32; o <<= 1) { int y = __shfl_up_sync(~0u, w, o); if (lane >= o) w += y; }
        ws[lane] = w;
    }
    __syncthreads();
    int incl = x + (wid > 0 ? ws[wid - 1] : 0);
    int total = ws[31];
    if (threadIdx.x == 0) {
        if (bid == 0) {
            atomicExch(&d_scan_state[0], (2ULL << 32) | (unsigned)total);
            s_pref = 0;
        } else {
            atomicExch(&d_scan_state[bid], (1ULL << 32) | (unsigned)total);
            int pref = 0;
            for (int j = bid - 1; j >= 0; --j) {
                unsigned long long st;
                do { st = atomicAdd(&d_scan_state[j], 0ULL); } while (!(st >> 32));
                pref += (int)(unsigned)st;
                if ((st >> 32) == 2ULL) break;
            }
            atomicExch(&d_scan_state[bid], (2ULL << 32) | (unsigned)(pref + total));
            s_pref = pref;
        }
    }
    __syncthreads();
    int pref = s_pref;
    if (i < n) d_off[i] = pref + incl - v;
    if (bid == nb - 1 && threadIdx.x == 0) d_off[n] = E;
}

__global__ void k_scatter(const int* __restrict__ src, const int* __restrict__ dst,
                          const int* __restrict__ perm, int E) {
    int e = blockIdx.x * blockDim.x + threadIdx.x;
    if (e < E) {
        int d = dst[e];
        int p = d_off[d] + atomicAdd(&d_cur[d], 1);
        d_adj[p] = make_int4(src[e], e, perm[e], 0);
    }
}

// ---------------- fused first-stage aggregation (bf16 tables, 128B rows) ----------------
__global__ void __launch_bounds__(256) k_agg3(int n) {
    int gw = (blockIdx.x * blockDim.x + threadIdx.x) >> 5;
    int lane = threadIdx.x & 31;
    if (gw >= n) return;
    int beg = d_off[gw], end = d_off[gw + 1];
    const uint32_t* nfb = reinterpret_cast<const uint32_t*>(d_nfb);
    const uint32_t* efb = reinterpret_cast<const uint32_t*>(d_efb);
    float2 ah = make_float2(0.f, 0.f), ap = ah, an = ah;
    int k = beg;
    for (; k + 4 <= end; k += 4) {
        int4 a0 = __ldg(&d_adj[k]);
        int4 a1 = __ldg(&d_adj[k + 1]);
        int4 a2 = __ldg(&d_adj[k + 2]);
        int4 a3 = __ldg(&d_adj[k + 3]);
        uint32_t h0 = __ldg(nfb + ((size_t)a0.x * 32 + lane));
        uint32_t p0 = __ldg(efb + ((size_t)a0.y * 32 + lane));
        uint32_t q0 = __ldg(efb + ((size_t)a0.z * 32 + lane));
        uint32_t h1 = __ldg(nfb + ((size_t)a1.x * 32 + lane));
        uint32_t p1 = __ldg(efb + ((size_t)a1.y * 32 + lane));
        uint32_t q1 = __ldg(efb + ((size_t)a1.z * 32 + lane));
        uint32_t h2 = __ldg(nfb + ((size_t)a2.x * 32 + lane));
        uint32_t p2 = __ldg(efb + ((size_t)a2.y * 32 + lane));
        uint32_t q2 = __ldg(efb + ((size_t)a2.z * 32 + lane));
        uint32_t h3 = __ldg(nfb + ((size_t)a3.x * 32 + lane));
        uint32_t p3 = __ldg(efb + ((size_t)a3.y * 32 + lane));
        uint32_t q3 = __ldg(efb + ((size_t)a3.z * 32 + lane));
        float2 t;
        t = bf2f(h0); ah.x += t.x; ah.y += t.y;
        t = bf2f(h1); ah.x += t.x; ah.y += t.y;
        t = bf2f(h2); ah.x += t.x; ah.y += t.y;
        t = bf2f(h3); ah.x += t.x; ah.y += t.y;
        t = bf2f(p0); ap.x += t.x; ap.y += t.y;
        t = bf2f(p1); ap.x += t.x; ap.y += t.y;
        t = bf2f(p2); ap.x += t.x; ap.y += t.y;
        t = bf2f(p3); ap.x += t.x; ap.y += t.y;
        t = bf2f(q0); an.x += t.x; an.y += t.y;
        t = bf2f(q1); an.x += t.x; an.y += t.y;
        t = bf2f(q2); an.x += t.x; an.y += t.y;
        t = bf2f(q3); an.x += t.x; an.y += t.y;
    }
    for (; k < end; ++k) {
        int4 a = __ldg(&d_adj[k]);
        float2 t;
        t = bf2f(__ldg(nfb + ((size_t)a.x * 32 + lane))); ah.x += t.x; ah.y += t.y;
        t = bf2f(__ldg(efb + ((size_t)a.y * 32 + lane))); ap.x += t.x; ap.y += t.y;
        t = bf2f(__ldg(efb + ((size_t)a.z * 32 + lane))); an.x += t.x; an.y += t.y;
    }
    float inv = 1.f / fmaxf((float)(end - beg), 1.f);
    reinterpret_cast<uint32_t*>(d_hagg0)[(size_t)gw * 32 + lane] = bf2(ah.x * inv, ah.y * inv);
    reinterpret_cast<uint32_t*>(d_efp)  [(size_t)gw * 32 + lane] = bf2(ap.x * inv, ap.y * inv);
    reinterpret_cast<uint32_t*>(d_efn)  [(size_t)gw * 32 + lane] = bf2(an.x * inv, an.y * inv);
}

// ---------------- second-stage aggregation: hp + hn (bf16 in/out, one pass) ----------------
__global__ void __launch_bounds__(256) k_aggh2(int n) {
    int gw = (blockIdx.x * blockDim.x + threadIdx.x) >> 5;
    int lane = threadIdx.x & 31;
    if (gw >= n) return;
    int beg = d_off[gw], end = d_off[gw + 1];
    const uint32_t* fa = reinterpret_cast<const uint32_t*>(d_h1p);
    const uint32_t* fb = reinterpret_cast<const uint32_t*>(d_h1n);
    const int* adjs = reinterpret_cast<const int*>(d_adj);
    float2 aa = make_float2(0.f, 0.f), ab = aa;
    int k = beg;
    for (; k + 4 <= end; k += 4) {
        int s0 = __ldg(adjs + 4 * k);
        int s1 = __ldg(adjs + 4 * (k + 1));
        int s2 = __ldg(adjs + 4 * (k + 2));
        int s3 = __ldg(adjs + 4 * (k + 3));
        uint32_t v0 = __ldg(fa + ((size_t)s0 * 32 + lane));
        uint32_t u0 = __ldg(fb + ((size_t)s0 * 32 + lane));
        uint32_t v1 = __ldg(fa + ((size_t)s1 * 32 + lane));
        uint32_t u1 = __ldg(fb + ((size_t)s1 * 32 + lane));
        uint32_t v2 = __ldg(fa + ((size_t)s2 * 32 + lane));
        uint32_t u2 = __ldg(fb + ((size_t)s2 * 32 + lane));
        uint32_t v3 = __ldg(fa + ((size_t)s3 * 32 + lane));
        uint32_t u3 = __ldg(fb + ((size_t)s3 * 32 + lane));
        float2 t;
        t = bf2f(v0); aa.x += t.x; aa.y += t.y;
        t = bf2f(v1); aa.x += t.x; aa.y += t.y;
        t = bf2f(v2); aa.x += t.x; aa.y += t.y;
        t = bf2f(v3); aa.x += t.x; aa.y += t.y;
        t = bf2f(u0); ab.x += t.x; ab.y += t.y;
        t = bf2f(u1); ab.x += t.x; ab.y += t.y;
        t = bf2f(u2); ab.x += t.x; ab.y += t.y;
        t = bf2f(u3); ab.x += t.x; ab.y += t.y;
    }
    for (; k < end; ++k) {
        int s = __ldg(adjs + 4 * k);
        float2 t;
        t = bf2f(__ldg(fa + ((size_t)s * 32 + lane))); aa.x += t.x; aa.y += t.y;
        t = bf2f(__ldg(fb + ((size_t)s * 32 + lane))); ab.x += t.x; ab.y += t.y;
    }
    float inv = 1.f / fmaxf((float)(end - beg), 1.f);
    reinterpret_cast<uint32_t*>(d_hp)[(size_t)gw * 32 + lane] = bf2(aa.x * inv, aa.y * inv);
    reinterpret_cast<uint32_t*>(d_hn)[(size_t)gw * 32 + lane] = bf2(ab.x * inv, ab.y * inv);
}

// ---------------- fold Wmsg into Wapply -> tf32 B-fragment layout ----------------
__global__ void k_fold2(const float* __restrict__ Wm0, const float* __restrict__ bm0,
                        const float* __restrict__ Wa0,
                        const float* __restrict__ Wm1, const float* __restrict__ bm1,
                        const float* __restrict__ Wa1) {
    int layer = blockIdx.x;
    const float* Wmsg = layer ? Wm1 : Wm0;
    const float* bmsg = layer ? bm1 : bm0;
    const float* Wap  = layer ? Wa1 : Wa0;
    __shared__ float Wn[64][64];
    __shared__ float bm[64];
    int tid = threadIdx.x;
    for (int idx = tid; idx < 64 * 64; idx += 256) {
        int j = idx >> 6, t = idx & 63;
        Wn[t][j] = Wap[j * 128 + 64 + t];
    }
    if (tid < 64) bm[tid] = bmsg[tid];
    __syncthreads();
    for (int idx = tid; idx < 192 * 64; idx += 256) {
        int k = idx >> 6, j = idx & 63;
        float r;
        if (k < 64) {
            r = Wap[j * 128 + k];
        } else {
            int col = k - 64;
            float a = 0.f;
            #pragma unroll
            for (int t = 0; t < 64; ++t) a += Wmsg[t * 128 + col] * Wn[t][j];
            r = a;
        }
        int panel = k >> 6, kk = k & 63;
        int s = kk >> 3, krem = kk & 7;
        int slot = krem >> 2, kq = krem & 3;
        int t = ((j & 7) << 2) | kq;
        int nb = j >> 3;
        int o = ((panel * 8 + s) * 8 + nb) * 64 + t * 2 + slot;
        d_Wf[layer][o] = tf32r(r);
    }
    for (int j = tid; j < 64; j += 256) {
        float a = 0.f;
        #pragma unroll
        for (int t = 0; t < 64; ++t) a += bm[t] * Wn[t][j];
        d_cv[layer][j] = a;
    }
}

// ---------------- mma GEMM building blocks ----------------
#define XST 68
#define SM_X 0
#define SM_W (128 * XST)
#define SM_B (SM_W + 64 * 64)
#define SM_C (SM_B + 64)
#define SM_TOTF (SM_C + 64)
#define GEMM_SMEM (SM_TOTF * 4)

__device__ __forceinline__ void stage_bf16(float* __restrict__ Xs, const __nv_bfloat16* __restrict__ S,
                                           int node0, int n, int tid) {
    #pragma unroll
    for (int it = 0; it < 4; ++it) {
        int t = tid + it * 256;
        int r = t >> 3, u4 = t & 7;
        int nd = node0 + r;
        uint4 v = make_uint4(0u, 0u, 0u, 0u);
        if (nd < n) v = __ldg(reinterpret_cast<const uint4*>(S) + (size_t)nd * 8 + u4);
        float2 f0 = bf2f(v.x), f1 = bf2f(v.y), f2 = bf2f(v.z), f3 = bf2f(v.w);
        *reinterpret_cast<float4*>(Xs + r * XST + u4 * 8)     = make_float4(f0.x, f0.y, f1.x, f1.y);
        *reinterpret_cast<float4*>(Xs + r * XST + u4 * 8 + 4) = make_float4(f2.x, f2.y, f3.x, f3.y);
    }
}
__device__ __forceinline__ void stage_w(float* __restrict__ Wp, const float* __restrict__ Wg, int tid) {
    #pragma unroll
    for (int it = 0; it < 4; ++it) {
        int t = tid + it * 256;
        reinterpret_cast<float4*>(Wp)[t] = __ldg(reinterpret_cast<const float4*>(Wg) + t);
    }
}
__device__ __forceinline__ void mma_phase(const float* __restrict__ Xs, const float* __restrict__ Wp,
                                          float* acc, int r0w, int lane) {
    int ar = r0w + (lane >> 2);
    #pragma unroll
    for (int s = 0; s < 8; ++s) {
        int ac = s * 8 + (lane & 3);
        uint32_t a0 = __float_as_uint(Xs[ar * XST + ac]);
        uint32_t a1 = __float_as_uint(Xs[(ar + 8) * XST + ac]);
        uint32_t a2 = __float_as_uint(Xs[ar * XST + ac + 4]);
        uint32_t a3 = __float_as_uint(Xs[(ar + 8) * XST + ac + 4]);
        #pragma unroll
        for (int nb = 0; nb < 8; ++nb) {
            float2 b = *reinterpret_cast<const float2*>(Wp + (s * 8 + nb) * 64 + lane * 2);
            mma_tf32(acc + nb * 4, a0, a1, a2, a3, __float_as_uint(b.x), __float_as_uint(b.y));
        }
    }
}

__device__ __forceinline__ float indf(int nd, int n) {
    return (nd < n && d_off[nd + 1] > d_off[nd]) ? 1.f : 0.f;
}

__device__ __forceinline__ void epi0(const float* acc, const float* __restrict__ sb,
                                     const float* __restrict__ sc, __nv_bfloat16* __restrict__ out,
                                     int node0, int r0w, int lane, int n) {
    int rA = node0 + r0w + (lane >> 2);
    int rB = rA + 8;
    float indA = indf(rA, n), indB = indf(rB, n);
    uint32_t* o32 = reinterpret_cast<uint32_t*>(out);
    #pragma unroll
    for (int nb = 0; nb < 8; ++nb) {
        int cc = nb * 8 + (lane & 3) * 2;
        float xA0 = fmaxf(acc[nb*4+0] + sb[cc]   + indA * sc[cc],   0.f);
        float xA1 = fmaxf(acc[nb*4+1] + sb[cc+1] + indA * sc[cc+1], 0.f);
        float xB0 = fmaxf(acc[nb*4+2] + sb[cc]   + indB * sc[cc],   0.f);
        float xB1 = fmaxf(acc[nb*4+3] + sb[cc+1] + indB * sc[cc+1], 0.f);
        if (rA < n) o32[(size_t)rA * 32 + (cc >> 1)] = bf2(xA0, xA1);
        if (rB < n) o32[(size_t)rB * 32 + (cc >> 1)] = bf2(xB0, xB1);
    }
}

// ---------------- layer 0 ----------------
__global__ void __launch_bounds__(256) k_l0(const float* __restrict__ bap, int n)
{
    extern __shared__ float sm[];
    float* Xs = sm + SM_X;
    float* Wp = sm + SM_W;
    float* sb = sm + SM_B;
    float* sc = sm + SM_C;
    int tid = threadIdx.x, wid = tid >> 5, lane = tid & 31;
    int node0 = blockIdx.x * 128;
    int r0w = wid * 16;
    if (tid < 64) { sb[tid] = bap[tid]; sc[tid] = d_cv[0][tid]; }

    float acc[32], accB[32];
    #pragma unroll
    for (int i = 0; i < 32; ++i) acc[i] = 0.f;

    stage_bf16(Xs, d_nfb, node0, n, tid);
    stage_w(Wp, d_Wf[0], tid);
    __syncthreads();
    mma_phase(Xs, Wp, acc, r0w, lane);
    __syncthreads();

    stage_bf16(Xs, d_hagg0, node0, n, tid);
    stage_w(Wp, d_Wf[0] + 4096, tid);
    __syncthreads();
    mma_phase(Xs, Wp, acc, r0w, lane);
    __syncthreads();
    #pragma unroll
    for (int i = 0; i < 32; ++i) accB[i] = acc[i];

    stage_bf16(Xs, d_efp, node0, n, tid);
    stage_w(Wp, d_Wf[0] + 8192, tid);
    __syncthreads();
    mma_phase(Xs, Wp, acc, r0w, lane);
    epi0(acc, sb, sc, d_h1p, node0, r0w, lane, n);
    __syncthreads();

    stage_bf16(Xs, d_efn, node0, n, tid);
    __syncthreads();
    #pragma unroll
    for (int i = 0; i < 32; ++i) acc[i] = accB[i];
    mma_phase(Xs, Wp, acc, r0w, lane);
    epi0(acc, sb, sc, d_h1n, node0, r0w, lane, n);
}

// ---------------- layer 1: 3 phases + fused BCE ----------------
__global__ void __launch_bounds__(256) k_l1(const float* __restrict__ bap, int n)
{
    extern __shared__ float sm[];
    float* Xs = sm + SM_X;
    float* Wp = sm + SM_W;
    float* sb = sm + SM_B;
    float* sc = sm + SM_C;
    __shared__ float wred[8];
    int tid = threadIdx.x, wid = tid >> 5, lane = tid & 31;
    int node0 = blockIdx.x * 128;
    int r0w = wid * 16;
    int view = blockIdx.y;
    if (tid < 64) { sb[tid] = bap[tid]; sc[tid] = d_cv[1][tid]; }

    const __nv_bfloat16* S0 = view ? d_h1n : d_h1p;
    const __nv_bfloat16* S1 = view ? d_hn  : d_hp;
    const __nv_bfloat16* S2 = view ? d_efn : d_efp;

    float acc[32];
    #pragma unroll
    for (int i = 0; i < 32; ++i) acc[i] = 0.f;

    #pragma unroll
    for (int p = 0; p < 3; ++p) {
        const __nv_bfloat16* S = (p == 0) ? S0 : (p == 1) ? S1 : S2;
        if (p) __syncthreads();
        stage_bf16(Xs, S, node0, n, tid);
        stage_w(Wp, d_Wf[1] + p * 4096, tid);
        __syncthreads();
        mma_phase(Xs, Wp, acc, r0w, lane);
    }

    int rA = node0 + r0w + (lane >> 2);
    int rB = rA + 8;
    float indA = indf(rA, n), indB = indf(rB, n);
    float lsum = 0.f;
    #pragma unroll
    for (int nb = 0; nb < 8; ++nb) {
        int cc = nb * 8 + (lane & 3) * 2;
        float xA0 = fmaxf(acc[nb*4+0] + sb[cc]   + indA * sc[cc],   0.f);
        float xA1 = fmaxf(acc[nb*4+1] + sb[cc+1] + indA * sc[cc+1], 0.f);
        float xB0 = fmaxf(acc[nb*4+2] + sb[cc]   + indB * sc[cc],   0.f);
        float xB1 = fmaxf(acc[nb*4+3] + sb[cc+1] + indB * sc[cc+1], 0.f);
        if (rA < n) {
            float t0 = log1pf(expf(-xA0)), t1 = log1pf(expf(-xA1));
            lsum += view ? (xA0 + t0 + xA1 + t1) : (t0 + t1);
        }
        if (rB < n) {
            float t0 = log1pf(expf(-xB0)), t1 = log1pf(expf(-xB1));
            lsum += view ? (xB0 + t0 + xB1 + t1) : (t0 + t1);
        }
    }
    #pragma unroll
    for (int o = 16; o; o >>= 1) lsum += __shfl_down_sync(~0u, lsum, o);
    if (lane == 0) wred[wid] = lsum;
    __syncthreads();
    if (tid < 8) {
        float s = wred[tid];
        #pragma unroll
        for (int o = 4; o; o >>= 1) s += __shfl_down_sync(0xffu, s, o);
        if (tid == 0) atomicAdd(&d_loss, (double)s);
    }
}

// ---------------- write result + restore zero-state invariant ----------------
__global__ void k_clean(float* out, double denom, int n) {
    int i = blockIdx.x * blockDim.x + threadIdx.x;
    if (i == 0) {
        out[0] = (float)(d_loss / denom);
        d_loss = 0.0;
        d_scan_tix = 0;
    }
    if (i < 128) d_scan_state[i] = 0ULL;
    if (i < n) { d_cnt[i] = 0; d_cur[i] = 0; }
}

// ---------------- launch ----------------
extern "C" void kernel_launch(void* const* d_in, const int* in_sizes, int n_in,
                              void* d_out, int out_size) {
    const float* nfeats = (const float*)d_in[0];
    const float* efeats = (const float*)d_in[1];
    const int*   src    = (const int*)d_in[2];
    const int*   dst    = (const int*)d_in[3];
    const int*   perm   = (const int*)d_in[4];
    const float* Wm0 = (const float*)d_in[5];
    const float* bm0 = (const float*)d_in[6];
    const float* Wa0 = (const float*)d_in[7];
    const float* ba0 = (const float*)d_in[8];
    const float* Wm1 = (const float*)d_in[9];
    const float* bm1 = (const float*)d_in[10];
    const float* Wa1 = (const float*)d_in[11];
    const float* ba1 = (const float*)d_in[12];

    int n = in_sizes[0] / 64;
    int E = in_sizes[2];
    int nb = (n + 1023) / 1024;

    cudaFuncSetAttribute(k_l0, cudaFuncAttributeMaxDynamicSharedMemorySize, GEMM_SMEM);
    cudaFuncSetAttribute(k_l1, cudaFuncAttributeMaxDynamicSharedMemorySize, GEMM_SMEM);

    int gw = (n * 32 + 255) / 256;  // one warp per node
    int gl = (n + 127) / 128;       // 128 nodes per tile

    k_histcvt<<<(E + 255) / 256, 256>>>(dst, efeats, nfeats, E, n);  // 1
    k_scan   <<<nb, 1024>>>(n, E, nb);                               // 2
    k_scatter<<<(E + 255) / 256, 256>>>(src, dst, perm, E);          // 3
    k_agg3   <<<gw, 256>>>(n);                                       // 4 <- profiled
    k_fold2  <<<2, 256>>>(Wm0, bm0, Wa0, Wm1, bm1, Wa1);             // 5
    k_l0     <<<gl, 256, GEMM_SMEM>>>(ba0, n);                       // 6
    k_aggh2  <<<gw, 256>>>(n);                                       // 7
    {
        dim3 grid(gl, 2);
        k_l1 <<<grid, 256, GEMM_SMEM>>>(ba1, n);                     // 8
    }
    k_clean  <<<(n + 255) / 256, 256>>>((float*)d_out, (double)n * 64.0, n); // 9
}

// round 12
// speedup vs baseline: 1.2495x; 1.0316x over previous
#include <cuda_runtime.h>
#include <cuda_bf16.h>
#include <math.h>
#include <cstdint>

#define NN 100000
#define EE 1000000

// ---------------- device scratch (zero-initialized at load; k_clean restores) ----------------
__device__ int    d_cnt[NN];
__device__ int    d_off[NN + 1];
__device__ int    d_cur[NN];
__device__ int    d_scan_tix;
__device__ unsigned long long d_scan_state[128];
__device__ int4   d_adj[EE];                    // {ssrc, eid, pid, 0}
__device__ __nv_bfloat16 d_efb [(size_t)EE * 64];   // bf16 copy of efeats (~L2-sized)
__device__ __nv_bfloat16 d_nfb [(size_t)NN * 64];   // bf16 copy of nfeats
__device__ __nv_bfloat16 d_hagg0[(size_t)NN * 64];
__device__ __nv_bfloat16 d_efp [(size_t)NN * 64];
__device__ __nv_bfloat16 d_efn [(size_t)NN * 64];
__device__ __nv_bfloat16 d_h1p [(size_t)NN * 64];
__device__ __nv_bfloat16 d_h1n [(size_t)NN * 64];
__device__ __nv_bfloat16 d_hp  [(size_t)NN * 64];
__device__ __nv_bfloat16 d_hn  [(size_t)NN * 64];
// folded W in tf32, stored in exact mma B-fragment order
__device__ float  d_Wf[2][3 * 8 * 8 * 64];
__device__ float  d_cv[2][64];
__device__ double d_loss;

// ---------------- helpers ----------------
__device__ __forceinline__ float tf32r(float x) {
    uint32_t r; asm("cvt.rna.tf32.f32 %0, %1;" : "=r"(r) : "f"(x));
    return __uint_as_float(r);
}
__device__ __forceinline__ void mma_tf32(float* c, uint32_t a0, uint32_t a1, uint32_t a2, uint32_t a3,
                                         uint32_t b0, uint32_t b1) {
    asm volatile("mma.sync.aligned.m16n8k8.row.col.f32.tf32.tf32.f32 "
                 "{%0,%1,%2,%3}, {%4,%5,%6,%7}, {%8,%9}, {%0,%1,%2,%3};"
                 : "+f"(c[0]), "+f"(c[1]), "+f"(c[2]), "+f"(c[3])
                 : "r"(a0), "r"(a1), "r"(a2), "r"(a3), "r"(b0), "r"(b1));
}
__device__ __forceinline__ uint32_t bf2(float x, float y) {
    uint32_t r; asm("cvt.rn.satfinite.bf16x2.f32 %0, %1, %2;" : "=r"(r) : "f"(y), "f"(x)); return r;
}
__device__ __forceinline__ float2 bf2f(uint32_t v) {
    __nv_bfloat162 h = *reinterpret_cast<__nv_bfloat162*>(&v);
    return __bfloat1622float2(h);
}
__device__ __forceinline__ uint32_t hadd2(uint32_t a, uint32_t b) {
    uint32_t r; asm("add.rn.bf16x2 %0, %1, %2;" : "=r"(r) : "r"(a), "r"(b)); return r;
}

// ---------------- CSR build + bf16 conversion (fused) ----------------
__global__ void __launch_bounds__(256) k_histcvt(const int* __restrict__ dst,
                                                 const float* __restrict__ ef,
                                                 const float* __restrict__ nf,
                                                 int E, int n) {
    int i = blockIdx.x * blockDim.x + threadIdx.x;
    int nth = gridDim.x * blockDim.x;
    if (i < E) atomicAdd(&d_cnt[dst[i]], 1);
    const float4* efi = reinterpret_cast<const float4*>(ef);
    uint4* efo = reinterpret_cast<uint4*>(d_efb);
    int tote = E * 8;                        // uint4 outputs (16B each)
    #pragma unroll 2
    for (int t = i; t < tote; t += nth) {
        float4 a = __ldg(efi + 2 * t);
        float4 b = __ldg(efi + 2 * t + 1);
        efo[t] = make_uint4(bf2(a.x, a.y), bf2(a.z, a.w), bf2(b.x, b.y), bf2(b.z, b.w));
    }
    const float4* nfi = reinterpret_cast<const float4*>(nf);
    uint4* nfo = reinterpret_cast<uint4*>(d_nfb);
    int totn = n * 8;
    #pragma unroll 2
    for (int t = i; t < totn; t += nth) {
        float4 a = __ldg(nfi + 2 * t);
        float4 b = __ldg(nfi + 2 * t + 1);
        nfo[t] = make_uint4(bf2(a.x, a.y), bf2(a.z, a.w), bf2(b.x, b.y), bf2(b.z, b.w));
    }
}

__global__ void k_scan(int n, int E, int nb) {
    __shared__ int ws[32];
    __shared__ int s_bid;
    __shared__ int s_pref;
    if (threadIdx.x == 0) s_bid = atomicAdd(&d_scan_tix, 1);
    __syncthreads();
    int bid = s_bid;
    int i = bid * 1024 + threadIdx.x;
    int lane = threadIdx.x & 31, wid = threadIdx.x >> 5;
    int v = (i < n) ? d_cnt[i] : 0;
    int x = v;
    #pragma unroll
    for (int o = 1; o < 32; o <<= 1) { int y = __shfl_up_sync(~0u, x, o); if (lane >= o) x += y; }
    if (lane == 31) ws[wid] = x;
    __syncthreads();
    if (wid == 0) {
        int w = ws[lane];
        #pragma unroll
        for (int o = 1; o < 32; o <<= 1) { int y = __shfl_up_sync(~0u, w, o); if (lane >= o) w += y; }
        ws[lane] = w;
    }
    __syncthreads();
    int incl = x + (wid > 0 ? ws[wid - 1] : 0);
    int total = ws[31];
    if (threadIdx.x == 0) {
        if (bid == 0) {
            atomicExch(&d_scan_state[0], (2ULL << 32) | (unsigned)total);
            s_pref = 0;
        } else {
            atomicExch(&d_scan_state[bid], (1ULL << 32) | (unsigned)total);
            int pref = 0;
            for (int j = bid - 1; j >= 0; --j) {
                unsigned long long st;
                do { st = atomicAdd(&d_scan_state[j], 0ULL); } while (!(st >> 32));
                pref += (int)(unsigned)st;
                if ((st >> 32) == 2ULL) break;
            }
            atomicExch(&d_scan_state[bid], (2ULL << 32) | (unsigned)(pref + total));
            s_pref = pref;
        }
    }
    __syncthreads();
    int pref = s_pref;
    if (i < n) d_off[i] = pref + incl - v;
    if (bid == nb - 1 && threadIdx.x == 0) d_off[n] = E;
}

__global__ void k_scatter(const int* __restrict__ src, const int* __restrict__ dst,
                          const int* __restrict__ perm, int E) {
    int e = blockIdx.x * blockDim.x + threadIdx.x;
    if (e < E) {
        int d = dst[e];
        int p = d_off[d] + atomicAdd(&d_cur[d], 1);
        d_adj[p] = make_int4(src[e], e, perm[e], 0);
    }
}

// ---------------- fused first-stage aggregation (bf16 tables + HADD2 tree) ----------------
__global__ void __launch_bounds__(256) k_agg3(int n) {
    int gw = (blockIdx.x * blockDim.x + threadIdx.x) >> 5;
    int lane = threadIdx.x & 31;
    if (gw >= n) return;
    int beg = d_off[gw], end = d_off[gw + 1];
    const uint32_t* nfb = reinterpret_cast<const uint32_t*>(d_nfb);
    const uint32_t* efb = reinterpret_cast<const uint32_t*>(d_efb);
    float2 ah = make_float2(0.f, 0.f), ap = ah, an = ah;
    int k = beg;
    for (; k + 4 <= end; k += 4) {
        int4 a0 = __ldg(&d_adj[k]);
        int4 a1 = __ldg(&d_adj[k + 1]);
        int4 a2 = __ldg(&d_adj[k + 2]);
        int4 a3 = __ldg(&d_adj[k + 3]);
        uint32_t h0 = __ldg(nfb + ((size_t)a0.x * 32 + lane));
        uint32_t p0 = __ldg(efb + ((size_t)a0.y * 32 + lane));
        uint32_t q0 = __ldg(efb + ((size_t)a0.z * 32 + lane));
        uint32_t h1 = __ldg(nfb + ((size_t)a1.x * 32 + lane));
        uint32_t p1 = __ldg(efb + ((size_t)a1.y * 32 + lane));
        uint32_t q1 = __ldg(efb + ((size_t)a1.z * 32 + lane));
        uint32_t h2 = __ldg(nfb + ((size_t)a2.x * 32 + lane));
        uint32_t p2 = __ldg(efb + ((size_t)a2.y * 32 + lane));
        uint32_t q2 = __ldg(efb + ((size_t)a2.z * 32 + lane));
        uint32_t h3 = __ldg(nfb + ((size_t)a3.x * 32 + lane));
        uint32_t p3 = __ldg(efb + ((size_t)a3.y * 32 + lane));
        uint32_t q3 = __ldg(efb + ((size_t)a3.z * 32 + lane));
        float2 t;
        t = bf2f(hadd2(hadd2(h0, h1), hadd2(h2, h3))); ah.x += t.x; ah.y += t.y;
        t = bf2f(hadd2(hadd2(p0, p1), hadd2(p2, p3))); ap.x += t.x; ap.y += t.y;
        t = bf2f(hadd2(hadd2(q0, q1), hadd2(q2, q3))); an.x += t.x; an.y += t.y;
    }
    for (; k < end; ++k) {
        int4 a = __ldg(&d_adj[k]);
        float2 t;
        t = bf2f(__ldg(nfb + ((size_t)a.x * 32 + lane))); ah.x += t.x; ah.y += t.y;
        t = bf2f(__ldg(efb + ((size_t)a.y * 32 + lane))); ap.x += t.x; ap.y += t.y;
        t = bf2f(__ldg(efb + ((size_t)a.z * 32 + lane))); an.x += t.x; an.y += t.y;
    }
    float inv = 1.f / fmaxf((float)(end - beg), 1.f);
    reinterpret_cast<uint32_t*>(d_hagg0)[(size_t)gw * 32 + lane] = bf2(ah.x * inv, ah.y * inv);
    reinterpret_cast<uint32_t*>(d_efp)  [(size_t)gw * 32 + lane] = bf2(ap.x * inv, ap.y * inv);
    reinterpret_cast<uint32_t*>(d_efn)  [(size_t)gw * 32 + lane] = bf2(an.x * inv, an.y * inv);
}

// ---------------- second-stage aggregation: hp + hn (bf16, HADD2 tree) ----------------
__global__ void __launch_bounds__(256) k_aggh2(int n) {
    int gw = (blockIdx.x * blockDim.x + threadIdx.x) >> 5;
    int lane = threadIdx.x & 31;
    if (gw >= n) return;
    int beg = d_off[gw], end = d_off[gw + 1];
    const uint32_t* fa = reinterpret_cast<const uint32_t*>(d_h1p);
    const uint32_t* fb = reinterpret_cast<const uint32_t*>(d_h1n);
    const int* adjs = reinterpret_cast<const int*>(d_adj);
    float2 aa = make_float2(0.f, 0.f), ab = aa;
    int k = beg;
    for (; k + 4 <= end; k += 4) {
        int s0 = __ldg(adjs + 4 * k);
        int s1 = __ldg(adjs + 4 * (k + 1));
        int s2 = __ldg(adjs + 4 * (k + 2));
        int s3 = __ldg(adjs + 4 * (k + 3));
        uint32_t v0 = __ldg(fa + ((size_t)s0 * 32 + lane));
        uint32_t u0 = __ldg(fb + ((size_t)s0 * 32 + lane));
        uint32_t v1 = __ldg(fa + ((size_t)s1 * 32 + lane));
        uint32_t u1 = __ldg(fb + ((size_t)s1 * 32 + lane));
        uint32_t v2 = __ldg(fa + ((size_t)s2 * 32 + lane));
        uint32_t u2 = __ldg(fb + ((size_t)s2 * 32 + lane));
        uint32_t v3 = __ldg(fa + ((size_t)s3 * 32 + lane));
        uint32_t u3 = __ldg(fb + ((size_t)s3 * 32 + lane));
        float2 t;
        t = bf2f(hadd2(hadd2(v0, v1), hadd2(v2, v3))); aa.x += t.x; aa.y += t.y;
        t = bf2f(hadd2(hadd2(u0, u1), hadd2(u2, u3))); ab.x += t.x; ab.y += t.y;
    }
    for (; k < end; ++k) {
        int s = __ldg(adjs + 4 * k);
        float2 t;
        t = bf2f(__ldg(fa + ((size_t)s * 32 + lane))); aa.x += t.x; aa.y += t.y;
        t = bf2f(__ldg(fb + ((size_t)s * 32 + lane))); ab.x += t.x; ab.y += t.y;
    }
    float inv = 1.f / fmaxf((float)(end - beg), 1.f);
    reinterpret_cast<uint32_t*>(d_hp)[(size_t)gw * 32 + lane] = bf2(aa.x * inv, aa.y * inv);
    reinterpret_cast<uint32_t*>(d_hn)[(size_t)gw * 32 + lane] = bf2(ab.x * inv, ab.y * inv);
}

// ---------------- fold Wmsg into Wapply -> tf32 B-fragment layout ----------------
__global__ void k_fold2(const float* __restrict__ Wm0, const float* __restrict__ bm0,
                        const float* __restrict__ Wa0,
                        const float* __restrict__ Wm1, const float* __restrict__ bm1,
                        const float* __restrict__ Wa1) {
    int layer = blockIdx.x;
    const float* Wmsg = layer ? Wm1 : Wm0;
    const float* bmsg = layer ? bm1 : bm0;
    const float* Wap  = layer ? Wa1 : Wa0;
    __shared__ float Wn[64][64];
    __shared__ float bm[64];
    int tid = threadIdx.x;
    for (int idx = tid; idx < 64 * 64; idx += 256) {
        int j = idx >> 6, t = idx & 63;
        Wn[t][j] = Wap[j * 128 + 64 + t];
    }
    if (tid < 64) bm[tid] = bmsg[tid];
    __syncthreads();
    for (int idx = tid; idx < 192 * 64; idx += 256) {
        int k = idx >> 6, j = idx & 63;
        float r;
        if (k < 64) {
            r = Wap[j * 128 + k];
        } else {
            int col = k - 64;
            float a = 0.f;
            #pragma unroll
            for (int t = 0; t < 64; ++t) a += Wmsg[t * 128 + col] * Wn[t][j];
            r = a;
        }
        int panel = k >> 6, kk = k & 63;
        int s = kk >> 3, krem = kk & 7;
        int slot = krem >> 2, kq = krem & 3;
        int t = ((j & 7) << 2) | kq;
        int nb = j >> 3;
        int o = ((panel * 8 + s) * 8 + nb) * 64 + t * 2 + slot;
        d_Wf[layer][o] = tf32r(r);
    }
    for (int j = tid; j < 64; j += 256) {
        float a = 0.f;
        #pragma unroll
        for (int t = 0; t < 64; ++t) a += bm[t] * Wn[t][j];
        d_cv[layer][j] = a;
    }
}

// ---------------- mma GEMM building blocks ----------------
#define XST 68
#define SM_X 0
#define SM_W (128 * XST)                 // 3 panels of 4096 floats
#define SM_B (SM_W + 3 * 4096)
#define SM_C (SM_B + 64)
#define SM_TOTF (SM_C + 64)
#define GEMM_SMEM (SM_TOTF * 4)

// prefetch next phase's X tile into registers (issued early, consumed after mma)
__device__ __forceinline__ void pf_load(uint4* pf, const __nv_bfloat16* __restrict__ S,
                                        int node0, int n, int tid) {
    #pragma unroll
    for (int it = 0; it < 4; ++it) {
        int t = tid + it * 256;
        int r = t >> 3, u4 = t & 7;
        int nd = node0 + r;
        pf[it] = make_uint4(0u, 0u, 0u, 0u);
        if (nd < n) pf[it] = __ldg(reinterpret_cast<const uint4*>(S) + (size_t)nd * 8 + u4);
    }
}
__device__ __forceinline__ void pf_store(float* __restrict__ Xs, const uint4* pf, int tid) {
    #pragma unroll
    for (int it = 0; it < 4; ++it) {
        int t = tid + it * 256;
        int r = t >> 3, u4 = t & 7;
        float2 f0 = bf2f(pf[it].x), f1 = bf2f(pf[it].y), f2 = bf2f(pf[it].z), f3 = bf2f(pf[it].w);
        *reinterpret_cast<float4*>(Xs + r * XST + u4 * 8)     = make_float4(f0.x, f0.y, f1.x, f1.y);
        *reinterpret_cast<float4*>(Xs + r * XST + u4 * 8 + 4) = make_float4(f2.x, f2.y, f3.x, f3.y);
    }
}
__device__ __forceinline__ void stage_w_all(float* __restrict__ Wp, const float* __restrict__ Wg, int tid) {
    #pragma unroll
    for (int it = 0; it < 12; ++it) {
        int t = tid + it * 256;
        reinterpret_cast<float4*>(Wp)[t] = __ldg(reinterpret_cast<const float4*>(Wg) + t);
    }
}
__device__ __forceinline__ void mma_phase(const float* __restrict__ Xs, const float* __restrict__ Wp,
                                          float* acc, int r0w, int lane) {
    int ar = r0w + (lane >> 2);
    #pragma unroll
    for (int s = 0; s < 8; ++s) {
        int ac = s * 8 + (lane & 3);
        uint32_t a0 = __float_as_uint(Xs[ar * XST + ac]);
        uint32_t a1 = __float_as_uint(Xs[(ar + 8) * XST + ac]);
        uint32_t a2 = __float_as_uint(Xs[ar * XST + ac + 4]);
        uint32_t a3 = __float_as_uint(Xs[(ar + 8) * XST + ac + 4]);
        #pragma unroll
        for (int nb = 0; nb < 8; ++nb) {
            float2 b = *reinterpret_cast<const float2*>(Wp + (s * 8 + nb) * 64 + lane * 2);
            mma_tf32(acc + nb * 4, a0, a1, a2, a3, __float_as_uint(b.x), __float_as_uint(b.y));
        }
    }
}

__device__ __forceinline__ float indf(int nd, int n) {
    return (nd < n && d_off[nd + 1] > d_off[nd]) ? 1.f : 0.f;
}

__device__ __forceinline__ void epi0(const float* acc, const float* __restrict__ sb,
                                     const float* __restrict__ sc, __nv_bfloat16* __restrict__ out,
                                     int node0, int r0w, int lane, int n) {
    int rA = node0 + r0w + (lane >> 2);
    int rB = rA + 8;
    float indA = indf(rA, n), indB = indf(rB, n);
    uint32_t* o32 = reinterpret_cast<uint32_t*>(out);
    #pragma unroll
    for (int nb = 0; nb < 8; ++nb) {
        int cc = nb * 8 + (lane & 3) * 2;
        float xA0 = fmaxf(acc[nb*4+0] + sb[cc]   + indA * sc[cc],   0.f);
        float xA1 = fmaxf(acc[nb*4+1] + sb[cc+1] + indA * sc[cc+1], 0.f);
        float xB0 = fmaxf(acc[nb*4+2] + sb[cc]   + indB * sc[cc],   0.f);
        float xB1 = fmaxf(acc[nb*4+3] + sb[cc+1] + indB * sc[cc+1], 0.f);
        if (rA < n) o32[(size_t)rA * 32 + (cc >> 1)] = bf2(xA0, xA1);
        if (rB < n) o32[(size_t)rB * 32 + (cc >> 1)] = bf2(xB0, xB1);
    }
}

// ---------------- layer 0 (software-pipelined staging) ----------------
__global__ void __launch_bounds__(256) k_l0(const float* __restrict__ bap, int n)
{
    extern __shared__ float sm[];
    float* Xs = sm + SM_X;
    float* Wp = sm + SM_W;
    float* sb = sm + SM_B;
    float* sc = sm + SM_C;
    int tid = threadIdx.x, wid = tid >> 5, lane = tid & 31;
    int node0 = blockIdx.x * 128;
    int r0w = wid * 16;
    if (tid < 64) { sb[tid] = bap[tid]; sc[tid] = d_cv[0][tid]; }
    stage_w_all(Wp, d_Wf[0], tid);

    float acc[32], accB[32];
    #pragma unroll
    for (int i = 0; i < 32; ++i) acc[i] = 0.f;

    uint4 pf[4];
    pf_load(pf, d_nfb, node0, n, tid);
    __syncthreads();
    pf_store(Xs, pf, tid);
    __syncthreads();
    pf_load(pf, d_hagg0, node0, n, tid);     // prefetch p1
    mma_phase(Xs, Wp, acc, r0w, lane);       // p0
    __syncthreads();
    pf_store(Xs, pf, tid);
    __syncthreads();
    pf_load(pf, d_efp, node0, n, tid);       // prefetch p2
    mma_phase(Xs, Wp + 4096, acc, r0w, lane);// p1
    #pragma unroll
    for (int i = 0; i < 32; ++i) accB[i] = acc[i];
    __syncthreads();
    pf_store(Xs, pf, tid);
    __syncthreads();
    pf_load(pf, d_efn, node0, n, tid);       // prefetch p3
    mma_phase(Xs, Wp + 8192, acc, r0w, lane);// p2
    epi0(acc, sb, sc, d_h1p, node0, r0w, lane, n);
    __syncthreads();
    pf_store(Xs, pf, tid);
    __syncthreads();
    #pragma unroll
    for (int i = 0; i < 32; ++i) acc[i] = accB[i];
    mma_phase(Xs, Wp + 8192, acc, r0w, lane);// p3
    epi0(acc, sb, sc, d_h1n, node0, r0w, lane, n);
}

// ---------------- layer 1 (software-pipelined, fused BCE) ----------------
__global__ void __launch_bounds__(256) k_l1(const float* __restrict__ bap, int n)
{
    extern __shared__ float sm[];
    float* Xs = sm + SM_X;
    float* Wp = sm + SM_W;
    float* sb = sm + SM_B;
    float* sc = sm + SM_C;
    __shared__ float wred[8];
    int tid = threadIdx.x, wid = tid >> 5, lane = tid & 31;
    int node0 = blockIdx.x * 128;
    int r0w = wid * 16;
    int view = blockIdx.y;
    if (tid < 64) { sb[tid] = bap[tid]; sc[tid] = d_cv[1][tid]; }
    stage_w_all(Wp, d_Wf[1], tid);

    const __nv_bfloat16* S0 = view ? d_h1n : d_h1p;
    const __nv_bfloat16* S1 = view ? d_hn  : d_hp;
    const __nv_bfloat16* S2 = view ? d_efn : d_efp;

    float acc[32];
    #pragma unroll
    for (int i = 0; i < 32; ++i) acc[i] = 0.f;

    uint4 pf[4];
    pf_load(pf, S0, node0, n, tid);
    __syncthreads();
    pf_store(Xs, pf, tid);
    __syncthreads();
    pf_load(pf, S1, node0, n, tid);
    mma_phase(Xs, Wp, acc, r0w, lane);
    __syncthreads();
    pf_store(Xs, pf, tid);
    __syncthreads();
    pf_load(pf, S2, node0, n, tid);
    mma_phase(Xs, Wp + 4096, acc, r0w, lane);
    __syncthreads();
    pf_store(Xs, pf, tid);
    __syncthreads();
    mma_phase(Xs, Wp + 8192, acc, r0w, lane);

    int rA = node0 + r0w + (lane >> 2);
    int rB = rA + 8;
    float indA = indf(rA, n), indB = indf(rB, n);
    float lsum = 0.f;
    #pragma unroll
    for (int nb = 0; nb < 8; ++nb) {
        int cc = nb * 8 + (lane & 3) * 2;
        float xA0 = fmaxf(acc[nb*4+0] + sb[cc]   + indA * sc[cc],   0.f);
        float xA1 = fmaxf(acc[nb*4+1] + sb[cc+1] + indA * sc[cc+1], 0.f);
        float xB0 = fmaxf(acc[nb*4+2] + sb[cc]   + indB * sc[cc],   0.f);
        float xB1 = fmaxf(acc[nb*4+3] + sb[cc+1] + indB * sc[cc+1], 0.f);
        if (rA < n) {
            float t0 = log1pf(expf(-xA0)), t1 = log1pf(expf(-xA1));
            lsum += view ? (xA0 + t0 + xA1 + t1) : (t0 + t1);
        }
        if (rB < n) {
            float t0 = log1pf(expf(-xB0)), t1 = log1pf(expf(-xB1));
            lsum += view ? (xB0 + t0 + xB1 + t1) : (t0 + t1);
        }
    }
    #pragma unroll
    for (int o = 16; o; o >>= 1) lsum += __shfl_down_sync(~0u, lsum, o);
    if (lane == 0) wred[wid] = lsum;
    __syncthreads();
    if (tid < 8) {
        float s = wred[tid];
        #pragma unroll
        for (int o = 4; o; o >>= 1) s += __shfl_down_sync(0xffu, s, o);
        if (tid == 0) atomicAdd(&d_loss, (double)s);
    }
}

// ---------------- write result + restore zero-state invariant ----------------
__global__ void k_clean(float* out, double denom, int n) {
    int i = blockIdx.x * blockDim.x + threadIdx.x;
    if (i == 0) {
        out[0] = (float)(d_loss / denom);
        d_loss = 0.0;
        d_scan_tix = 0;
    }
    if (i < 128) d_scan_state[i] = 0ULL;
    if (i < n) { d_cnt[i] = 0; d_cur[i] = 0; }
}

// ---------------- launch ----------------
extern "C" void kernel_launch(void* const* d_in, const int* in_sizes, int n_in,
                              void* d_out, int out_size) {
    const float* nfeats = (const float*)d_in[0];
    const float* efeats = (const float*)d_in[1];
    const int*   src    = (const int*)d_in[2];
    const int*   dst    = (const int*)d_in[3];
    const int*   perm   = (const int*)d_in[4];
    const float* Wm0 = (const float*)d_in[5];
    const float* bm0 = (const float*)d_in[6];
    const float* Wa0 = (const float*)d_in[7];
    const float* ba0 = (const float*)d_in[8];
    const float* Wm1 = (const float*)d_in[9];
    const float* bm1 = (const float*)d_in[10];
    const float* Wa1 = (const float*)d_in[11];
    const float* ba1 = (const float*)d_in[12];

    int n = in_sizes[0] / 64;
    int E = in_sizes[2];
    int nb = (n + 1023) / 1024;

    cudaFuncSetAttribute(k_l0, cudaFuncAttributeMaxDynamicSharedMemorySize, GEMM_SMEM);
    cudaFuncSetAttribute(k_l1, cudaFuncAttributeMaxDynamicSharedMemorySize, GEMM_SMEM);

    int gw = (n * 32 + 255) / 256;  // one warp per node
    int gl = (n + 127) / 128;       // 128 nodes per tile

    k_histcvt<<<(E + 255) / 256, 256>>>(dst, efeats, nfeats, E, n);  // 1
    k_scan   <<<nb, 1024>>>(n, E, nb);                               // 2
    k_scatter<<<(E + 255) / 256, 256>>>(src, dst, perm, E);          // 3
    k_agg3   <<<gw, 256>>>(n);                                       // 4 <- profiled
    k_fold2  <<<2, 256>>>(Wm0, bm0, Wa0, Wm1, bm1, Wa1);             // 5
    k_l0     <<<gl, 256, GEMM_SMEM>>>(ba0, n);                       // 6
    k_aggh2  <<<gw, 256>>>(n);                                       // 7
    {
        dim3 grid(gl, 2);
        k_l1 <<<grid, 256, GEMM_SMEM>>>(ba1, n);                     // 8
    }
    k_clean  <<<(n + 255) / 256, 256>>>((float*)d_out, (double)n * 64.0, n); // 9
}

// round 13
// speedup vs baseline: 1.2602x; 1.0085x over previous
#include <cuda_runtime.h>
#include <cuda_bf16.h>
#include <math.h>
#include <cstdint>

#define NN 100000
#define EE 1000000

// ---------------- device scratch (zero-initialized at load; k_clean restores) ----------------
__device__ int    d_cnt[NN];
__device__ int    d_off[NN + 1];
__device__ int    d_cur[NN];
__device__ int    d_scan_tix;
__device__ unsigned long long d_scan_state[128];
__device__ int4   d_adj[EE];                    // {ssrc, eid, pid, 0}
__device__ __nv_bfloat16 d_efb [(size_t)EE * 64];   // bf16 copy of efeats (~L2-sized)
__device__ __nv_bfloat16 d_nfb [(size_t)NN * 64];   // bf16 copy of nfeats
__device__ __nv_bfloat16 d_hagg0[(size_t)NN * 64];
__device__ __nv_bfloat16 d_efp [(size_t)NN * 64];
__device__ __nv_bfloat16 d_efn [(size_t)NN * 64];
__device__ __nv_bfloat16 d_h1p [(size_t)NN * 64];
__device__ __nv_bfloat16 d_h1n [(size_t)NN * 64];
__device__ __nv_bfloat16 d_hp  [(size_t)NN * 64];
__device__ __nv_bfloat16 d_hn  [(size_t)NN * 64];
// folded W in tf32, stored in exact mma B-fragment order
__device__ float  d_Wf[2][3 * 8 * 8 * 64];
__device__ float  d_cv[2][64];
__device__ double d_loss;

// ---------------- helpers ----------------
__device__ __forceinline__ float tf32r(float x) {
    uint32_t r; asm("cvt.rna.tf32.f32 %0, %1;" : "=r"(r) : "f"(x));
    return __uint_as_float(r);
}
__device__ __forceinline__ void mma_tf32(float* c, uint32_t a0, uint32_t a1, uint32_t a2, uint32_t a3,
                                         uint32_t b0, uint32_t b1) {
    asm volatile("mma.sync.aligned.m16n8k8.row.col.f32.tf32.tf32.f32 "
                 "{%0,%1,%2,%3}, {%4,%5,%6,%7}, {%8,%9}, {%0,%1,%2,%3};"
                 : "+f"(c[0]), "+f"(c[1]), "+f"(c[2]), "+f"(c[3])
                 : "r"(a0), "r"(a1), "r"(a2), "r"(a3), "r"(b0), "r"(b1));
}
__device__ __forceinline__ uint32_t bf2(float x, float y) {
    uint32_t r; asm("cvt.rn.satfinite.bf16x2.f32 %0, %1, %2;" : "=r"(r) : "f"(y), "f"(x)); return r;
}
__device__ __forceinline__ float2 bf2f(uint32_t v) {
    __nv_bfloat162 h = *reinterpret_cast<__nv_bfloat162*>(&v);
    return __bfloat1622float2(h);
}
__device__ __forceinline__ uint32_t hadd2(uint32_t a, uint32_t b) {
    uint32_t r; asm("add.rn.bf16x2 %0, %1, %2;" : "=r"(r) : "r"(a), "r"(b)); return r;
}

// ---------------- CSR build with conversion hidden under latency-bound kernels ----------------
// k_hist: histogram atomics + convert FIRST half of efeats (streaming overlaps atomics)
__global__ void __launch_bounds__(256) k_hist(const int* __restrict__ dst,
                                              const float* __restrict__ ef, int E) {
    int i = blockIdx.x * blockDim.x + threadIdx.x;
    int nth = gridDim.x * blockDim.x;
    if (i < E) atomicAdd(&d_cnt[dst[i]], 1);
    const float4* efi = reinterpret_cast<const float4*>(ef);
    uint4* efo = reinterpret_cast<uint4*>(d_efb);
    int half = E * 4;                         // first half: uint4 chunks [0, E*8/2)
    #pragma unroll 2
    for (int t = i; t < half; t += nth) {
        float4 a = __ldg(efi + 2 * t);
        float4 b = __ldg(efi + 2 * t + 1);
        efo[t] = make_uint4(bf2(a.x, a.y), bf2(a.z, a.w), bf2(b.x, b.y), bf2(b.z, b.w));
    }
}

__global__ void k_scan(int n, int E, int nb) {
    __shared__ int ws[32];
    __shared__ int s_bid;
    __shared__ int s_pref;
    if (threadIdx.x == 0) s_bid = atomicAdd(&d_scan_tix, 1);
    __syncthreads();
    int bid = s_bid;
    int i = bid * 1024 + threadIdx.x;
    int lane = threadIdx.x & 31, wid = threadIdx.x >> 5;
    int v = (i < n) ? d_cnt[i] : 0;
    int x = v;
    #pragma unroll
    for (int o = 1; o < 32; o <<= 1) { int y = __shfl_up_sync(~0u, x, o); if (lane >= o) x += y; }
    if (lane == 31) ws[wid] = x;
    __syncthreads();
    if (wid == 0) {
        int w = ws[lane];
        #pragma unroll
        for (int o = 1; o < 32; o <<= 1) { int y = __shfl_up_sync(~0u, w, o); if (lane >= o) w += y; }
        ws[lane] = w;
    }
    __syncthreads();
    int incl = x + (wid > 0 ? ws[wid - 1] : 0);
    int total = ws[31];
    if (threadIdx.x == 0) {
        if (bid == 0) {
            atomicExch(&d_scan_state[0], (2ULL << 32) | (unsigned)total);
            s_pref = 0;
        } else {
            atomicExch(&d_scan_state[bid], (1ULL << 32) | (unsigned)total);
            int pref = 0;
            for (int j = bid - 1; j >= 0; --j) {
                unsigned long long st;
                do { st = atomicAdd(&d_scan_state[j], 0ULL); } while (!(st >> 32));
                pref += (int)(unsigned)st;
                if ((st >> 32) == 2ULL) break;
            }
            atomicExch(&d_scan_state[bid], (2ULL << 32) | (unsigned)(pref + total));
            s_pref = pref;
        }
    }
    __syncthreads();
    int pref = s_pref;
    if (i < n) d_off[i] = pref + incl - v;
    if (bid == nb - 1 && threadIdx.x == 0) d_off[n] = E;
}

// k_scatter: CSR scatter + convert SECOND half of efeats + nfeats
__global__ void __launch_bounds__(256) k_scatter(const int* __restrict__ src,
                                                 const int* __restrict__ dst,
                                                 const int* __restrict__ perm,
                                                 const float* __restrict__ ef,
                                                 const float* __restrict__ nf,
                                                 int E, int n) {
    int i = blockIdx.x * blockDim.x + threadIdx.x;
    int nth = gridDim.x * blockDim.x;
    if (i < E) {
        int d = dst[i];
        int p = d_off[d] + atomicAdd(&d_cur[d], 1);
        d_adj[p] = make_int4(src[i], i, perm[i], 0);
    }
    const float4* efi = reinterpret_cast<const float4*>(ef);
    uint4* efo = reinterpret_cast<uint4*>(d_efb);
    int half = E * 4, tote = E * 8;           // second half: [E*4, E*8)
    #pragma unroll 2
    for (int t = i + half; t < tote; t += nth) {
        float4 a = __ldg(efi + 2 * t);
        float4 b = __ldg(efi + 2 * t + 1);
        efo[t] = make_uint4(bf2(a.x, a.y), bf2(a.z, a.w), bf2(b.x, b.y), bf2(b.z, b.w));
    }
    const float4* nfi = reinterpret_cast<const float4*>(nf);
    uint4* nfo = reinterpret_cast<uint4*>(d_nfb);
    int totn = n * 8;
    for (int t = i; t < totn; t += nth) {
        float4 a = __ldg(nfi + 2 * t);
        float4 b = __ldg(nfi + 2 * t + 1);
        nfo[t] = make_uint4(bf2(a.x, a.y), bf2(a.z, a.w), bf2(b.x, b.y), bf2(b.z, b.w));
    }
}

// ---------------- fused first-stage aggregation (bf16 tables + HADD2 tree) ----------------
__global__ void __launch_bounds__(256) k_agg3(int n) {
    int gw = (blockIdx.x * blockDim.x + threadIdx.x) >> 5;
    int lane = threadIdx.x & 31;
    if (gw >= n) return;
    int beg = d_off[gw], end = d_off[gw + 1];
    const uint32_t* nfb = reinterpret_cast<const uint32_t*>(d_nfb);
    const uint32_t* efb = reinterpret_cast<const uint32_t*>(d_efb);
    float2 ah = make_float2(0.f, 0.f), ap = ah, an = ah;
    int k = beg;
    for (; k + 4 <= end; k += 4) {
        int4 a0 = __ldg(&d_adj[k]);
        int4 a1 = __ldg(&d_adj[k + 1]);
        int4 a2 = __ldg(&d_adj[k + 2]);
        int4 a3 = __ldg(&d_adj[k + 3]);
        uint32_t h0 = __ldg(nfb + ((size_t)a0.x * 32 + lane));
        uint32_t p0 = __ldg(efb + ((size_t)a0.y * 32 + lane));
        uint32_t q0 = __ldg(efb + ((size_t)a0.z * 32 + lane));
        uint32_t h1 = __ldg(nfb + ((size_t)a1.x * 32 + lane));
        uint32_t p1 = __ldg(efb + ((size_t)a1.y * 32 + lane));
        uint32_t q1 = __ldg(efb + ((size_t)a1.z * 32 + lane));
        uint32_t h2 = __ldg(nfb + ((size_t)a2.x * 32 + lane));
        uint32_t p2 = __ldg(efb + ((size_t)a2.y * 32 + lane));
        uint32_t q2 = __ldg(efb + ((size_t)a2.z * 32 + lane));
        uint32_t h3 = __ldg(nfb + ((size_t)a3.x * 32 + lane));
        uint32_t p3 = __ldg(efb + ((size_t)a3.y * 32 + lane));
        uint32_t q3 = __ldg(efb + ((size_t)a3.z * 32 + lane));
        float2 t;
        t = bf2f(hadd2(hadd2(h0, h1), hadd2(h2, h3))); ah.x += t.x; ah.y += t.y;
        t = bf2f(hadd2(hadd2(p0, p1), hadd2(p2, p3))); ap.x += t.x; ap.y += t.y;
        t = bf2f(hadd2(hadd2(q0, q1), hadd2(q2, q3))); an.x += t.x; an.y += t.y;
    }
    for (; k < end; ++k) {
        int4 a = __ldg(&d_adj[k]);
        float2 t;
        t = bf2f(__ldg(nfb + ((size_t)a.x * 32 + lane))); ah.x += t.x; ah.y += t.y;
        t = bf2f(__ldg(efb + ((size_t)a.y * 32 + lane))); ap.x += t.x; ap.y += t.y;
        t = bf2f(__ldg(efb + ((size_t)a.z * 32 + lane))); an.x += t.x; an.y += t.y;
    }
    float inv = 1.f / fmaxf((float)(end - beg), 1.f);
    reinterpret_cast<uint32_t*>(d_hagg0)[(size_t)gw * 32 + lane] = bf2(ah.x * inv, ah.y * inv);
    reinterpret_cast<uint32_t*>(d_efp)  [(size_t)gw * 32 + lane] = bf2(ap.x * inv, ap.y * inv);
    reinterpret_cast<uint32_t*>(d_efn)  [(size_t)gw * 32 + lane] = bf2(an.x * inv, an.y * inv);
}

// ---------------- second-stage aggregation: hp + hn (bf16, HADD2 tree) ----------------
__global__ void __launch_bounds__(256) k_aggh2(int n) {
    int gw = (blockIdx.x * blockDim.x + threadIdx.x) >> 5;
    int lane = threadIdx.x & 31;
    if (gw >= n) return;
    int beg = d_off[gw], end = d_off[gw + 1];
    const uint32_t* fa = reinterpret_cast<const uint32_t*>(d_h1p);
    const uint32_t* fb = reinterpret_cast<const uint32_t*>(d_h1n);
    const int* adjs = reinterpret_cast<const int*>(d_adj);
    float2 aa = make_float2(0.f, 0.f), ab = aa;
    int k = beg;
    for (; k + 4 <= end; k += 4) {
        int s0 = __ldg(adjs + 4 * k);
        int s1 = __ldg(adjs + 4 * (k + 1));
        int s2 = __ldg(adjs + 4 * (k + 2));
        int s3 = __ldg(adjs + 4 * (k + 3));
        uint32_t v0 = __ldg(fa + ((size_t)s0 * 32 + lane));
        uint32_t u0 = __ldg(fb + ((size_t)s0 * 32 + lane));
        uint32_t v1 = __ldg(fa + ((size_t)s1 * 32 + lane));
        uint32_t u1 = __ldg(fb + ((size_t)s1 * 32 + lane));
        uint32_t v2 = __ldg(fa + ((size_t)s2 * 32 + lane));
        uint32_t u2 = __ldg(fb + ((size_t)s2 * 32 + lane));
        uint32_t v3 = __ldg(fa + ((size_t)s3 * 32 + lane));
        uint32_t u3 = __ldg(fb + ((size_t)s3 * 32 + lane));
        float2 t;
        t = bf2f(hadd2(hadd2(v0, v1), hadd2(v2, v3))); aa.x += t.x; aa.y += t.y;
        t = bf2f(hadd2(hadd2(u0, u1), hadd2(u2, u3))); ab.x += t.x; ab.y += t.y;
    }
    for (; k < end; ++k) {
        int s = __ldg(adjs + 4 * k);
        float2 t;
        t = bf2f(__ldg(fa + ((size_t)s * 32 + lane))); aa.x += t.x; aa.y += t.y;
        t = bf2f(__ldg(fb + ((size_t)s * 32 + lane))); ab.x += t.x; ab.y += t.y;
    }
    float inv = 1.f / fmaxf((float)(end - beg), 1.f);
    reinterpret_cast<uint32_t*>(d_hp)[(size_t)gw * 32 + lane] = bf2(aa.x * inv, aa.y * inv);
    reinterpret_cast<uint32_t*>(d_hn)[(size_t)gw * 32 + lane] = bf2(ab.x * inv, ab.y * inv);
}

// ---------------- fold Wmsg into Wapply -> tf32 B-fragment layout ----------------
__global__ void k_fold2(const float* __restrict__ Wm0, const float* __restrict__ bm0,
                        const float* __restrict__ Wa0,
                        const float* __restrict__ Wm1, const float* __restrict__ bm1,
                        const float* __restrict__ Wa1) {
    int layer = blockIdx.x;
    const float* Wmsg = layer ? Wm1 : Wm0;
    const float* bmsg = layer ? bm1 : bm0;
    const float* Wap  = layer ? Wa1 : Wa0;
    __shared__ float Wn[64][64];
    __shared__ float bm[64];
    int tid = threadIdx.x;
    for (int idx = tid; idx < 64 * 64; idx += 256) {
        int j = idx >> 6, t = idx & 63;
        Wn[t][j] = Wap[j * 128 + 64 + t];
    }
    if (tid < 64) bm[tid] = bmsg[tid];
    __syncthreads();
    for (int idx = tid; idx < 192 * 64; idx += 256) {
        int k = idx >> 6, j = idx & 63;
        float r;
        if (k < 64) {
            r = Wap[j * 128 + k];
        } else {
            int col = k - 64;
            float a = 0.f;
            #pragma unroll
            for (int t = 0; t < 64; ++t) a += Wmsg[t * 128 + col] * Wn[t][j];
            r = a;
        }
        int panel = k >> 6, kk = k & 63;
        int s = kk >> 3, krem = kk & 7;
        int slot = krem >> 2, kq = krem & 3;
        int t = ((j & 7) << 2) | kq;
        int nb = j >> 3;
        int o = ((panel * 8 + s) * 8 + nb) * 64 + t * 2 + slot;
        d_Wf[layer][o] = tf32r(r);
    }
    for (int j = tid; j < 64; j += 256) {
        float a = 0.f;
        #pragma unroll
        for (int t = 0; t < 64; ++t) a += bm[t] * Wn[t][j];
        d_cv[layer][j] = a;
    }
}

// ---------------- mma GEMM building blocks ----------------
#define XST 68
#define SM_X 0
#define SM_W (128 * XST)                 // 3 panels of 4096 floats
#define SM_B (SM_W + 3 * 4096)
#define SM_C (SM_B + 64)
#define SM_TOTF (SM_C + 64)
#define GEMM_SMEM (SM_TOTF * 4)

// prefetch next phase's X tile into registers (issued early, consumed after mma)
__device__ __forceinline__ void pf_load(uint4* pf, const __nv_bfloat16* __restrict__ S,
                                        int node0, int n, int tid) {
    #pragma unroll
    for (int it = 0; it < 4; ++it) {
        int t = tid + it * 256;
        int r = t >> 3, u4 = t & 7;
        int nd = node0 + r;
        pf[it] = make_uint4(0u, 0u, 0u, 0u);
        if (nd < n) pf[it] = __ldg(reinterpret_cast<const uint4*>(S) + (size_t)nd * 8 + u4);
    }
}
__device__ __forceinline__ void pf_store(float* __restrict__ Xs, const uint4* pf, int tid) {
    #pragma unroll
    for (int it = 0; it < 4; ++it) {
        int t = tid + it * 256;
        int r = t >> 3, u4 = t & 7;
        float2 f0 = bf2f(pf[it].x), f1 = bf2f(pf[it].y), f2 = bf2f(pf[it].z), f3 = bf2f(pf[it].w);
        *reinterpret_cast<float4*>(Xs + r * XST + u4 * 8)     = make_float4(f0.x, f0.y, f1.x, f1.y);
        *reinterpret_cast<float4*>(Xs + r * XST + u4 * 8 + 4) = make_float4(f2.x, f2.y, f3.x, f3.y);
    }
}
__device__ __forceinline__ void stage_w_all(float* __restrict__ Wp, const float* __restrict__ Wg, int tid) {
    #pragma unroll
    for (int it = 0; it < 12; ++it) {
        int t = tid + it * 256;
        reinterpret_cast<float4*>(Wp)[t] = __ldg(reinterpret_cast<const float4*>(Wg) + t);
    }
}
__device__ __forceinline__ void mma_phase(const float* __restrict__ Xs, const float* __restrict__ Wp,
                                          float* acc, int r0w, int lane) {
    int ar = r0w + (lane >> 2);
    #pragma unroll
    for (int s = 0; s < 8; ++s) {
        int ac = s * 8 + (lane & 3);
        uint32_t a0 = __float_as_uint(Xs[ar * XST + ac]);
        uint32_t a1 = __float_as_uint(Xs[(ar + 8) * XST + ac]);
        uint32_t a2 = __float_as_uint(Xs[ar * XST + ac + 4]);
        uint32_t a3 = __float_as_uint(Xs[(ar + 8) * XST + ac + 4]);
        #pragma unroll
        for (int nb = 0; nb < 8; ++nb) {
            float2 b = *reinterpret_cast<const float2*>(Wp + (s * 8 + nb) * 64 + lane * 2);
            mma_tf32(acc + nb * 4, a0, a1, a2, a3, __float_as_uint(b.x), __float_as_uint(b.y));
        }
    }
}

__device__ __forceinline__ float indf(int nd, int n) {
    return (nd < n && d_off[nd + 1] > d_off[nd]) ? 1.f : 0.f;
}

__device__ __forceinline__ void epi0(const float* acc, const float* __restrict__ sb,
                                     const float* __restrict__ sc, __nv_bfloat16* __restrict__ out,
                                     int node0, int r0w, int lane, int n) {
    int rA = node0 + r0w + (lane >> 2);
    int rB = rA + 8;
    float indA = indf(rA, n), indB = indf(rB, n);
    uint32_t* o32 = reinterpret_cast<uint32_t*>(out);
    #pragma unroll
    for (int nb = 0; nb < 8; ++nb) {
        int cc = nb * 8 + (lane & 3) * 2;
        float xA0 = fmaxf(acc[nb*4+0] + sb[cc]   + indA * sc[cc],   0.f);
        float xA1 = fmaxf(acc[nb*4+1] + sb[cc+1] + indA * sc[cc+1], 0.f);
        float xB0 = fmaxf(acc[nb*4+2] + sb[cc]   + indB * sc[cc],   0.f);
        float xB1 = fmaxf(acc[nb*4+3] + sb[cc+1] + indB * sc[cc+1], 0.f);
        if (rA < n) o32[(size_t)rA * 32 + (cc >> 1)] = bf2(xA0, xA1);
        if (rB < n) o32[(size_t)rB * 32 + (cc >> 1)] = bf2(xB0, xB1);
    }
}

// ---------------- layer 0 (software-pipelined staging) ----------------
__global__ void __launch_bounds__(256) k_l0(const float* __restrict__ bap, int n)
{
    extern __shared__ float sm[];
    float* Xs = sm + SM_X;
    float* Wp = sm + SM_W;
    float* sb = sm + SM_B;
    float* sc = sm + SM_C;
    int tid = threadIdx.x, wid = tid >> 5, lane = tid & 31;
    int node0 = blockIdx.x * 128;
    int r0w = wid * 16;
    if (tid < 64) { sb[tid] = bap[tid]; sc[tid] = d_cv[0][tid]; }
    stage_w_all(Wp, d_Wf[0], tid);

    float acc[32], accB[32];
    #pragma unroll
    for (int i = 0; i < 32; ++i) acc[i] = 0.f;

    uint4 pf[4];
    pf_load(pf, d_nfb, node0, n, tid);
    __syncthreads();
    pf_store(Xs, pf, tid);
    __syncthreads();
    pf_load(pf, d_hagg0, node0, n, tid);     // prefetch p1
    mma_phase(Xs, Wp, acc, r0w, lane);       // p0
    __syncthreads();
    pf_store(Xs, pf, tid);
    __syncthreads();
    pf_load(pf, d_efp, node0, n, tid);       // prefetch p2
    mma_phase(Xs, Wp + 4096, acc, r0w, lane);// p1
    #pragma unroll
    for (int i = 0; i < 32; ++i) accB[i] = acc[i];
    __syncthreads();
    pf_store(Xs, pf, tid);
    __syncthreads();
    pf_load(pf, d_efn, node0, n, tid);       // prefetch p3
    mma_phase(Xs, Wp + 8192, acc, r0w, lane);// p2
    epi0(acc, sb, sc, d_h1p, node0, r0w, lane, n);
    __syncthreads();
    pf_store(Xs, pf, tid);
    __syncthreads();
    #pragma unroll
    for (int i = 0; i < 32; ++i) acc[i] = accB[i];
    mma_phase(Xs, Wp + 8192, acc, r0w, lane);// p3
    epi0(acc, sb, sc, d_h1n, node0, r0w, lane, n);
}

// ---------------- layer 1 (software-pipelined, fused BCE) ----------------
__global__ void __launch_bounds__(256) k_l1(const float* __restrict__ bap, int n)
{
    extern __shared__ float sm[];
    float* Xs = sm + SM_X;
    float* Wp = sm + SM_W;
    float* sb = sm + SM_B;
    float* sc = sm + SM_C;
    __shared__ float wred[8];
    int tid = threadIdx.x, wid = tid >> 5, lane = tid & 31;
    int node0 = blockIdx.x * 128;
    int r0w = wid * 16;
    int view = blockIdx.y;
    if (tid < 64) { sb[tid] = bap[tid]; sc[tid] = d_cv[1][tid]; }
    stage_w_all(Wp, d_Wf[1], tid);

    const __nv_bfloat16* S0 = view ? d_h1n : d_h1p;
    const __nv_bfloat16* S1 = view ? d_hn  : d_hp;
    const __nv_bfloat16* S2 = view ? d_efn : d_efp;

    float acc[32];
    #pragma unroll
    for (int i = 0; i < 32; ++i) acc[i] = 0.f;

    uint4 pf[4];
    pf_load(pf, S0, node0, n, tid);
    __syncthreads();
    pf_store(Xs, pf, tid);
    __syncthreads();
    pf_load(pf, S1, node0, n, tid);
    mma_phase(Xs, Wp, acc, r0w, lane);
    __syncthreads();
    pf_store(Xs, pf, tid);
    __syncthreads();
    pf_load(pf, S2, node0, n, tid);
    mma_phase(Xs, Wp + 4096, acc, r0w, lane);
    __syncthreads();
    pf_store(Xs, pf, tid);
    __syncthreads();
    mma_phase(Xs, Wp + 8192, acc, r0w, lane);

    int rA = node0 + r0w + (lane >> 2);
    int rB = rA + 8;
    float indA = indf(rA, n), indB = indf(rB, n);
    float lsum = 0.f;
    #pragma unroll
    for (int nb = 0; nb < 8; ++nb) {
        int cc = nb * 8 + (lane & 3) * 2;
        float xA0 = fmaxf(acc[nb*4+0] + sb[cc]   + indA * sc[cc],   0.f);
        float xA1 = fmaxf(acc[nb*4+1] + sb[cc+1] + indA * sc[cc+1], 0.f);
        float xB0 = fmaxf(acc[nb*4+2] + sb[cc]   + indB * sc[cc],   0.f);
        float xB1 = fmaxf(acc[nb*4+3] + sb[cc+1] + indB * sc[cc+1], 0.f);
        if (rA < n) {
            float t0 = log1pf(expf(-xA0)), t1 = log1pf(expf(-xA1));
            lsum += view ? (xA0 + t0 + xA1 + t1) : (t0 + t1);
        }
        if (rB < n) {
            float t0 = log1pf(expf(-xB0)), t1 = log1pf(expf(-xB1));
            lsum += view ? (xB0 + t0 + xB1 + t1) : (t0 + t1);
        }
    }
    #pragma unroll
    for (int o = 16; o; o >>= 1) lsum += __shfl_down_sync(~0u, lsum, o);
    if (lane == 0) wred[wid] = lsum;
    __syncthreads();
    if (tid < 8) {
        float s = wred[tid];
        #pragma unroll
        for (int o = 4; o; o >>= 1) s += __shfl_down_sync(0xffu, s, o);
        if (tid == 0) atomicAdd(&d_loss, (double)s);
    }
}

// ---------------- write result + restore zero-state invariant ----------------
__global__ void k_clean(float* out, double denom, int n) {
    int i = blockIdx.x * blockDim.x + threadIdx.x;
    if (i == 0) {
        out[0] = (float)(d_loss / denom);
        d_loss = 0.0;
        d_scan_tix = 0;
    }
    if (i < 128) d_scan_state[i] = 0ULL;
    if (i < n) { d_cnt[i] = 0; d_cur[i] = 0; }
}

// ---------------- launch ----------------
extern "C" void kernel_launch(void* const* d_in, const int* in_sizes, int n_in,
                              void* d_out, int out_size) {
    const float* nfeats = (const float*)d_in[0];
    const float* efeats = (const float*)d_in[1];
    const int*   src    = (const int*)d_in[2];
    const int*   dst    = (const int*)d_in[3];
    const int*   perm   = (const int*)d_in[4];
    const float* Wm0 = (const float*)d_in[5];
    const float* bm0 = (const float*)d_in[6];
    const float* Wa0 = (const float*)d_in[7];
    const float* ba0 = (const float*)d_in[8];
    const float* Wm1 = (const float*)d_in[9];
    const float* bm1 = (const float*)d_in[10];
    const float* Wa1 = (const float*)d_in[11];
    const float* ba1 = (const float*)d_in[12];

    int n = in_sizes[0] / 64;
    int E = in_sizes[2];
    int nb = (n + 1023) / 1024;

    cudaFuncSetAttribute(k_l0, cudaFuncAttributeMaxDynamicSharedMemorySize, GEMM_SMEM);
    cudaFuncSetAttribute(k_l1, cudaFuncAttributeMaxDynamicSharedMemorySize, GEMM_SMEM);

    int gw = (n * 32 + 255) / 256;  // one warp per node
    int gl = (n + 127) / 128;       // 128 nodes per tile

    k_hist   <<<(E + 255) / 256, 256>>>(dst, efeats, E);                    // 1 (+ ef cvt half)
    k_scan   <<<nb, 1024>>>(n, E, nb);                                      // 2
    k_scatter<<<(E + 255) / 256, 256>>>(src, dst, perm, efeats, nfeats, E, n); // 3 (+ ef/nf cvt)
    k_agg3   <<<gw, 256>>>(n);                                              // 4 <- profiled
    k_fold2  <<<2, 256>>>(Wm0, bm0, Wa0, Wm1, bm1, Wa1);                    // 5
    k_l0     <<<gl, 256, GEMM_SMEM>>>(ba0, n);                              // 6
    k_aggh2  <<<gw, 256>>>(n);                                              // 7
    {
        dim3 grid(gl, 2);
        k_l1 <<<grid, 256, GEMM_SMEM>>>(ba1, n);                            // 8
    }
    k_clean  <<<(n + 255) / 256, 256>>>((float*)d_out, (double)n * 64.0, n); // 9
}

// round 14
// speedup vs baseline: 1.2663x; 1.0048x over previous
#include <cuda_runtime.h>
#include <cuda_bf16.h>
#include <math.h>
#include <cstdint>

#define NN 100000
#define EE 1000000

// ---------------- device scratch (zero-initialized at load; k_clean restores) ----------------
__device__ int    d_cnt[NN];
__device__ int    d_off[NN + 1];
__device__ int    d_cur[NN];
__device__ int    d_scan_tix;
__device__ unsigned long long d_scan_state[128];
__device__ int4   d_adj[EE];                    // {ssrc, eid, pid, 0}
__device__ __nv_bfloat16 d_nfb [(size_t)NN * 64];   // bf16 copy of nfeats
__device__ __nv_bfloat16 d_hagg0[(size_t)NN * 64];
__device__ __nv_bfloat16 d_efp [(size_t)NN * 64];
__device__ __nv_bfloat16 d_efn [(size_t)NN * 64];
__device__ __nv_bfloat16 d_h1p [(size_t)NN * 64];
__device__ __nv_bfloat16 d_h1n [(size_t)NN * 64];
__device__ __nv_bfloat16 d_hp  [(size_t)NN * 64];
__device__ __nv_bfloat16 d_hn  [(size_t)NN * 64];
// folded W in tf32, stored in exact mma B-fragment order
__device__ float  d_Wf[2][3 * 8 * 8 * 64];
__device__ float  d_cv[2][64];
__device__ double d_loss;

// ---------------- helpers ----------------
__device__ __forceinline__ float tf32r(float x) {
    uint32_t r; asm("cvt.rna.tf32.f32 %0, %1;" : "=r"(r) : "f"(x));
    return __uint_as_float(r);
}
__device__ __forceinline__ void mma_tf32(float* c, uint32_t a0, uint32_t a1, uint32_t a2, uint32_t a3,
                                         uint32_t b0, uint32_t b1) {
    asm volatile("mma.sync.aligned.m16n8k8.row.col.f32.tf32.tf32.f32 "
                 "{%0,%1,%2,%3}, {%4,%5,%6,%7}, {%8,%9}, {%0,%1,%2,%3};"
                 : "+f"(c[0]), "+f"(c[1]), "+f"(c[2]), "+f"(c[3])
                 : "r"(a0), "r"(a1), "r"(a2), "r"(a3), "r"(b0), "r"(b1));
}
__device__ __forceinline__ uint32_t bf2(float x, float y) {
    uint32_t r; asm("cvt.rn.satfinite.bf16x2.f32 %0, %1, %2;" : "=r"(r) : "f"(y), "f"(x)); return r;
}
__device__ __forceinline__ float2 bf2f(uint32_t v) {
    __nv_bfloat162 h = *reinterpret_cast<__nv_bfloat162*>(&v);
    return __bfloat1622float2(h);
}
__device__ __forceinline__ uint32_t hadd2(uint32_t a, uint32_t b) {
    uint32_t r; asm("add.rn.bf16x2 %0, %1, %2;" : "=r"(r) : "r"(a), "r"(b)); return r;
}

// ---------------- CSR build ----------------
__global__ void k_hist(const int* __restrict__ dst, int E) {
    int e = blockIdx.x * blockDim.x + threadIdx.x;
    if (e < E) atomicAdd(&d_cnt[dst[e]], 1);
}

__global__ void k_scan(int n, int E, int nb) {
    __shared__ int ws[32];
    __shared__ int s_bid;
    __shared__ int s_pref;
    if (threadIdx.x == 0) s_bid = atomicAdd(&d_scan_tix, 1);
    __syncthreads();
    int bid = s_bid;
    int i = bid * 1024 + threadIdx.x;
    int lane = threadIdx.x & 31, wid = threadIdx.x >> 5;
    int v = (i < n) ? d_cnt[i] : 0;
    int x = v;
    #pragma unroll
    for (int o = 1; o < 32; o <<= 1) { int y = __shfl_up_sync(~0u, x, o); if (lane >= o) x += y; }
    if (lane == 31) ws[wid] = x;
    __syncthreads();
    if (wid == 0) {
        int w = ws[lane];
        #pragma unroll
        for (int o = 1; o < 32; o <<= 1) { int y = __shfl_up_sync(~0u, w, o); if (lane >= o) w += y; }
        ws[lane] = w;
    }
    __syncthreads();
    int incl = x + (wid > 0 ? ws[wid - 1] : 0);
    int total = ws[31];
    if (threadIdx.x == 0) {
        if (bid == 0) {
            atomicExch(&d_scan_state[0], (2ULL << 32) | (unsigned)total);
            s_pref = 0;
        } else {
            atomicExch(&d_scan_state[bid], (1ULL << 32) | (unsigned)total);
            int pref = 0;
            for (int j = bid - 1; j >= 0; --j) {
                unsigned long long st;
                do { st = atomicAdd(&d_scan_state[j], 0ULL); } while (!(st >> 32));
                pref += (int)(unsigned)st;
                if ((st >> 32) == 2ULL) break;
            }
            atomicExch(&d_scan_state[bid], (2ULL << 32) | (unsigned)(pref + total));
            s_pref = pref;
        }
    }
    __syncthreads();
    int pref = s_pref;
    if (i < n) d_off[i] = pref + incl - v;
    if (bid == nb - 1 && threadIdx.x == 0) d_off[n] = E;
}

// k_scatter: CSR scatter + nfeats->bf16 conversion (small, hides under scatter latency)
__global__ void __launch_bounds__(256) k_scatter(const int* __restrict__ src,
                                                 const int* __restrict__ dst,
                                                 const int* __restrict__ perm,
                                                 const float* __restrict__ nf,
                                                 int E, int n) {
    int i = blockIdx.x * blockDim.x + threadIdx.x;
    int nth = gridDim.x * blockDim.x;
    if (i < E) {
        int d = dst[i];
        int p = d_off[d] + atomicAdd(&d_cur[d], 1);
        d_adj[p] = make_int4(src[i], i, perm[i], 0);
    }
    const float4* nfi = reinterpret_cast<const float4*>(nf);
    uint4* nfo = reinterpret_cast<uint4*>(d_nfb);
    int totn = n * 8;
    for (int t = i; t < totn; t += nth) {
        float4 a = __ldg(nfi + 2 * t);
        float4 b = __ldg(nfi + 2 * t + 1);
        nfo[t] = make_uint4(bf2(a.x, a.y), bf2(a.z, a.w), bf2(b.x, b.y), bf2(b.z, b.w));
    }
}

// ---------------- fused first-stage aggregation ----------------
// nf from bf16 table (HADD2 tree); ef gathered in fp32 directly (no conversion pass).
__global__ void __launch_bounds__(256) k_agg3(const float* __restrict__ ef, int n) {
    int gw = (blockIdx.x * blockDim.x + threadIdx.x) >> 5;
    int lane = threadIdx.x & 31;
    if (gw >= n) return;
    int beg = d_off[gw], end = d_off[gw + 1];
    const uint32_t* nfb = reinterpret_cast<const uint32_t*>(d_nfb);
    const float2* ef2 = reinterpret_cast<const float2*>(ef);
    float2 ah = make_float2(0.f, 0.f), ap = ah, an = ah;
    int k = beg;
    for (; k + 4 <= end; k += 4) {
        int4 a0 = __ldg(&d_adj[k]);
        int4 a1 = __ldg(&d_adj[k + 1]);
        int4 a2 = __ldg(&d_adj[k + 2]);
        int4 a3 = __ldg(&d_adj[k + 3]);
        uint32_t h0 = __ldg(nfb + ((size_t)a0.x * 32 + lane));
        float2 p0 = __ldg(ef2 + ((size_t)a0.y * 32 + lane));
        float2 q0 = __ldg(ef2 + ((size_t)a0.z * 32 + lane));
        uint32_t h1 = __ldg(nfb + ((size_t)a1.x * 32 + lane));
        float2 p1 = __ldg(ef2 + ((size_t)a1.y * 32 + lane));
        float2 q1 = __ldg(ef2 + ((size_t)a1.z * 32 + lane));
        uint32_t h2 = __ldg(nfb + ((size_t)a2.x * 32 + lane));
        float2 p2 = __ldg(ef2 + ((size_t)a2.y * 32 + lane));
        float2 q2 = __ldg(ef2 + ((size_t)a2.z * 32 + lane));
        uint32_t h3 = __ldg(nfb + ((size_t)a3.x * 32 + lane));
        float2 p3 = __ldg(ef2 + ((size_t)a3.y * 32 + lane));
        float2 q3 = __ldg(ef2 + ((size_t)a3.z * 32 + lane));
        float2 t = bf2f(hadd2(hadd2(h0, h1), hadd2(h2, h3)));
        ah.x += t.x; ah.y += t.y;
        ap.x += (p0.x + p1.x) + (p2.x + p3.x);
        ap.y += (p0.y + p1.y) + (p2.y + p3.y);
        an.x += (q0.x + q1.x) + (q2.x + q3.x);
        an.y += (q0.y + q1.y) + (q2.y + q3.y);
    }
    for (; k < end; ++k) {
        int4 a = __ldg(&d_adj[k]);
        float2 t = bf2f(__ldg(nfb + ((size_t)a.x * 32 + lane)));
        ah.x += t.x; ah.y += t.y;
        float2 p = __ldg(ef2 + ((size_t)a.y * 32 + lane));
        float2 q = __ldg(ef2 + ((size_t)a.z * 32 + lane));
        ap.x += p.x; ap.y += p.y;
        an.x += q.x; an.y += q.y;
    }
    float inv = 1.f / fmaxf((float)(end - beg), 1.f);
    reinterpret_cast<uint32_t*>(d_hagg0)[(size_t)gw * 32 + lane] = bf2(ah.x * inv, ah.y * inv);
    reinterpret_cast<uint32_t*>(d_efp)  [(size_t)gw * 32 + lane] = bf2(ap.x * inv, ap.y * inv);
    reinterpret_cast<uint32_t*>(d_efn)  [(size_t)gw * 32 + lane] = bf2(an.x * inv, an.y * inv);
}

// ---------------- second-stage aggregation: hp + hn (bf16, HADD2 tree) ----------------
__global__ void __launch_bounds__(256) k_aggh2(int n) {
    int gw = (blockIdx.x * blockDim.x + threadIdx.x) >> 5;
    int lane = threadIdx.x & 31;
    if (gw >= n) return;
    int beg = d_off[gw], end = d_off[gw + 1];
    const uint32_t* fa = reinterpret_cast<const uint32_t*>(d_h1p);
    const uint32_t* fb = reinterpret_cast<const uint32_t*>(d_h1n);
    const int* adjs = reinterpret_cast<const int*>(d_adj);
    float2 aa = make_float2(0.f, 0.f), ab = aa;
    int k = beg;
    for (; k + 4 <= end; k += 4) {
        int s0 = __ldg(adjs + 4 * k);
        int s1 = __ldg(adjs + 4 * (k + 1));
        int s2 = __ldg(adjs + 4 * (k + 2));
        int s3 = __ldg(adjs + 4 * (k + 3));
        uint32_t v0 = __ldg(fa + ((size_t)s0 * 32 + lane));
        uint32_t u0 = __ldg(fb + ((size_t)s0 * 32 + lane));
        uint32_t v1 = __ldg(fa + ((size_t)s1 * 32 + lane));
        uint32_t u1 = __ldg(fb + ((size_t)s1 * 32 + lane));
        uint32_t v2 = __ldg(fa + ((size_t)s2 * 32 + lane));
        uint32_t u2 = __ldg(fb + ((size_t)s2 * 32 + lane));
        uint32_t v3 = __ldg(fa + ((size_t)s3 * 32 + lane));
        uint32_t u3 = __ldg(fb + ((size_t)s3 * 32 + lane));
        float2 t;
        t = bf2f(hadd2(hadd2(v0, v1), hadd2(v2, v3))); aa.x += t.x; aa.y += t.y;
        t = bf2f(hadd2(hadd2(u0, u1), hadd2(u2, u3))); ab.x += t.x; ab.y += t.y;
    }
    for (; k < end; ++k) {
        int s = __ldg(adjs + 4 * k);
        float2 t;
        t = bf2f(__ldg(fa + ((size_t)s * 32 + lane))); aa.x += t.x; aa.y += t.y;
        t = bf2f(__ldg(fb + ((size_t)s * 32 + lane))); ab.x += t.x; ab.y += t.y;
    }
    float inv = 1.f / fmaxf((float)(end - beg), 1.f);
    reinterpret_cast<uint32_t*>(d_hp)[(size_t)gw * 32 + lane] = bf2(aa.x * inv, aa.y * inv);
    reinterpret_cast<uint32_t*>(d_hn)[(size_t)gw * 32 + lane] = bf2(ab.x * inv, ab.y * inv);
}

// ---------------- fold Wmsg into Wapply -> tf32 B-fragment layout ----------------
__global__ void k_fold2(const float* __restrict__ Wm0, const float* __restrict__ bm0,
                        const float* __restrict__ Wa0,
                        const float* __restrict__ Wm1, const float* __restrict__ bm1,
                        const float* __restrict__ Wa1) {
    int layer = blockIdx.x;
    const float* Wmsg = layer ? Wm1 : Wm0;
    const float* bmsg = layer ? bm1 : bm0;
    const float* Wap  = layer ? Wa1 : Wa0;
    __shared__ float Wn[64][64];
    __shared__ float bm[64];
    int tid = threadIdx.x;
    for (int idx = tid; idx < 64 * 64; idx += 256) {
        int j = idx >> 6, t = idx & 63;
        Wn[t][j] = Wap[j * 128 + 64 + t];
    }
    if (tid < 64) bm[tid] = bmsg[tid];
    __syncthreads();
    for (int idx = tid; idx < 192 * 64; idx += 256) {
        int k = idx >> 6, j = idx & 63;
        float r;
        if (k < 64) {
            r = Wap[j * 128 + k];
        } else {
            int col = k - 64;
            float a = 0.f;
            #pragma unroll
            for (int t = 0; t < 64; ++t) a += Wmsg[t * 128 + col] * Wn[t][j];
            r = a;
        }
        int panel = k >> 6, kk = k & 63;
        int s = kk >> 3, krem = kk & 7;
        int slot = krem >> 2, kq = krem & 3;
        int t = ((j & 7) << 2) | kq;
        int nb = j >> 3;
        int o = ((panel * 8 + s) * 8 + nb) * 64 + t * 2 + slot;
        d_Wf[layer][o] = tf32r(r);
    }
    for (int j = tid; j < 64; j += 256) {
        float a = 0.f;
        #pragma unroll
        for (int t = 0; t < 64; ++t) a += bm[t] * Wn[t][j];
        d_cv[layer][j] = a;
    }
}

// ---------------- mma GEMM building blocks ----------------
#define XST 68
#define SM_X 0
#define SM_W (128 * XST)                 // 3 panels of 4096 floats
#define SM_B (SM_W + 3 * 4096)
#define SM_C (SM_B + 64)
#define SM_TOTF (SM_C + 64)
#define GEMM_SMEM (SM_TOTF * 4)

__device__ __forceinline__ void pf_load(uint4* pf, const __nv_bfloat16* __restrict__ S,
                                        int node0, int n, int tid) {
    #pragma unroll
    for (int it = 0; it < 4; ++it) {
        int t = tid + it * 256;
        int r = t >> 3, u4 = t & 7;
        int nd = node0 + r;
        pf[it] = make_uint4(0u, 0u, 0u, 0u);
        if (nd < n) pf[it] = __ldg(reinterpret_cast<const uint4*>(S) + (size_t)nd * 8 + u4);
    }
}
__device__ __forceinline__ void pf_store(float* __restrict__ Xs, const uint4* pf, int tid) {
    #pragma unroll
    for (int it = 0; it < 4; ++it) {
        int t = tid + it * 256;
        int r = t >> 3, u4 = t & 7;
        float2 f0 = bf2f(pf[it].x), f1 = bf2f(pf[it].y), f2 = bf2f(pf[it].z), f3 = bf2f(pf[it].w);
        *reinterpret_cast<float4*>(Xs + r * XST + u4 * 8)     = make_float4(f0.x, f0.y, f1.x, f1.y);
        *reinterpret_cast<float4*>(Xs + r * XST + u4 * 8 + 4) = make_float4(f2.x, f2.y, f3.x, f3.y);
    }
}
__device__ __forceinline__ void stage_w_all(float* __restrict__ Wp, const float* __restrict__ Wg, int tid) {
    #pragma unroll
    for (int it = 0; it < 12; ++it) {
        int t = tid + it * 256;
        reinterpret_cast<float4*>(Wp)[t] = __ldg(reinterpret_cast<const float4*>(Wg) + t);
    }
}
__device__ __forceinline__ void mma_phase(const float* __restrict__ Xs, const float* __restrict__ Wp,
                                          float* acc, int r0w, int lane) {
    int ar = r0w + (lane >> 2);
    #pragma unroll
    for (int s = 0; s < 8; ++s) {
        int ac = s * 8 + (lane & 3);
        uint32_t a0 = __float_as_uint(Xs[ar * XST + ac]);
        uint32_t a1 = __float_as_uint(Xs[(ar + 8) * XST + ac]);
        uint32_t a2 = __float_as_uint(Xs[ar * XST + ac + 4]);
        uint32_t a3 = __float_as_uint(Xs[(ar + 8) * XST + ac + 4]);
        #pragma unroll
        for (int nb = 0; nb < 8; ++nb) {
            float2 b = *reinterpret_cast<const float2*>(Wp + (s * 8 + nb) * 64 + lane * 2);
            mma_tf32(acc + nb * 4, a0, a1, a2, a3, __float_as_uint(b.x), __float_as_uint(b.y));
        }
    }
}

__device__ __forceinline__ float indf(int nd, int n) {
    return (nd < n && d_off[nd + 1] > d_off[nd]) ? 1.f : 0.f;
}

__device__ __forceinline__ void epi0(const float* acc, const float* __restrict__ sb,
                                     const float* __restrict__ sc, __nv_bfloat16* __restrict__ out,
                                     int node0, int r0w, int lane, int n) {
    int rA = node0 + r0w + (lane >> 2);
    int rB = rA + 8;
    float indA = indf(rA, n), indB = indf(rB, n);
    uint32_t* o32 = reinterpret_cast<uint32_t*>(out);
    #pragma unroll
    for (int nb = 0; nb < 8; ++nb) {
        int cc = nb * 8 + (lane & 3) * 2;
        float xA0 = fmaxf(acc[nb*4+0] + sb[cc]   + indA * sc[cc],   0.f);
        float xA1 = fmaxf(acc[nb*4+1] + sb[cc+1] + indA * sc[cc+1], 0.f);
        float xB0 = fmaxf(acc[nb*4+2] + sb[cc]   + indB * sc[cc],   0.f);
        float xB1 = fmaxf(acc[nb*4+3] + sb[cc+1] + indB * sc[cc+1], 0.f);
        if (rA < n) o32[(size_t)rA * 32 + (cc >> 1)] = bf2(xA0, xA1);
        if (rB < n) o32[(size_t)rB * 32 + (cc >> 1)] = bf2(xB0, xB1);
    }
}

// ---------------- layer 0 (software-pipelined staging) ----------------
__global__ void __launch_bounds__(256) k_l0(const float* __restrict__ bap, int n)
{
    extern __shared__ float sm[];
    float* Xs = sm + SM_X;
    float* Wp = sm + SM_W;
    float* sb = sm + SM_B;
    float* sc = sm + SM_C;
    int tid = threadIdx.x, wid = tid >> 5, lane = tid & 31;
    int node0 = blockIdx.x * 128;
    int r0w = wid * 16;
    if (tid < 64) { sb[tid] = bap[tid]; sc[tid] = d_cv[0][tid]; }
    stage_w_all(Wp, d_Wf[0], tid);

    float acc[32], accB[32];
    #pragma unroll
    for (int i = 0; i < 32; ++i) acc[i] = 0.f;

    uint4 pf[4];
    pf_load(pf, d_nfb, node0, n, tid);
    __syncthreads();
    pf_store(Xs, pf, tid);
    __syncthreads();
    pf_load(pf, d_hagg0, node0, n, tid);     // prefetch p1
    mma_phase(Xs, Wp, acc, r0w, lane);       // p0
    __syncthreads();
    pf_store(Xs, pf, tid);
    __syncthreads();
    pf_load(pf, d_efp, node0, n, tid);       // prefetch p2
    mma_phase(Xs, Wp + 4096, acc, r0w, lane);// p1
    #pragma unroll
    for (int i = 0; i < 32; ++i) accB[i] = acc[i];
    __syncthreads();
    pf_store(Xs, pf, tid);
    __syncthreads();
    pf_load(pf, d_efn, node0, n, tid);       // prefetch p3
    mma_phase(Xs, Wp + 8192, acc, r0w, lane);// p2
    epi0(acc, sb, sc, d_h1p, node0, r0w, lane, n);
    __syncthreads();
    pf_store(Xs, pf, tid);
    __syncthreads();
    #pragma unroll
    for (int i = 0; i < 32; ++i) acc[i] = accB[i];
    mma_phase(Xs, Wp + 8192, acc, r0w, lane);// p3
    epi0(acc, sb, sc, d_h1n, node0, r0w, lane, n);
}

// ---------------- layer 1 (software-pipelined, fused BCE) ----------------
__global__ void __launch_bounds__(256) k_l1(const float* __restrict__ bap, int n)
{
    extern __shared__ float sm[];
    float* Xs = sm + SM_X;
    float* Wp = sm + SM_W;
    float* sb = sm + SM_B;
    float* sc = sm + SM_C;
    __shared__ float wred[8];
    int tid = threadIdx.x, wid = tid >> 5, lane = tid & 31;
    int node0 = blockIdx.x * 128;
    int r0w = wid * 16;
    int view = blockIdx.y;
    if (tid < 64) { sb[tid] = bap[tid]; sc[tid] = d_cv[1][tid]; }
    stage_w_all(Wp, d_Wf[1], tid);

    const __nv_bfloat16* S0 = view ? d_h1n : d_h1p;
    const __nv_bfloat16* S1 = view ? d_hn  : d_hp;
    const __nv_bfloat16* S2 = view ? d_efn : d_efp;

    float acc[32];
    #pragma unroll
    for (int i = 0; i < 32; ++i) acc[i] = 0.f;

    uint4 pf[4];
    pf_load(pf, S0, node0, n, tid);
    __syncthreads();
    pf_store(Xs, pf, tid);
    __syncthreads();
    pf_load(pf, S1, node0, n, tid);
    mma_phase(Xs, Wp, acc, r0w, lane);
    __syncthreads();
    pf_store(Xs, pf, tid);
    __syncthreads();
    pf_load(pf, S2, node0, n, tid);
    mma_phase(Xs, Wp + 4096, acc, r0w, lane);
    __syncthreads();
    pf_store(Xs, pf, tid);
    __syncthreads();
    mma_phase(Xs, Wp + 8192, acc, r0w, lane);

    int rA = node0 + r0w + (lane >> 2);
    int rB = rA + 8;
    float indA = indf(rA, n), indB = indf(rB, n);
    float lsum = 0.f;
    #pragma unroll
    for (int nb = 0; nb < 8; ++nb) {
        int cc = nb * 8 + (lane & 3) * 2;
        float xA0 = fmaxf(acc[nb*4+0] + sb[cc]   + indA * sc[cc],   0.f);
        float xA1 = fmaxf(acc[nb*4+1] + sb[cc+1] + indA * sc[cc+1], 0.f);
        float xB0 = fmaxf(acc[nb*4+2] + sb[cc]   + indB * sc[cc],   0.f);
        float xB1 = fmaxf(acc[nb*4+3] + sb[cc+1] + indB * sc[cc+1], 0.f);
        if (rA < n) {
            float t0 = log1pf(expf(-xA0)), t1 = log1pf(expf(-xA1));
            lsum += view ? (xA0 + t0 + xA1 + t1) : (t0 + t1);
        }
        if (rB < n) {
            float t0 = log1pf(expf(-xB0)), t1 = log1pf(expf(-xB1));
            lsum += view ? (xB0 + t0 + xB1 + t1) : (t0 + t1);
        }
    }
    #pragma unroll
    for (int o = 16; o; o >>= 1) lsum += __shfl_down_sync(~0u, lsum, o);
    if (lane == 0) wred[wid] = lsum;
    __syncthreads();
    if (tid < 8) {
        float s = wred[tid];
        #pragma unroll
        for (int o = 4; o; o >>= 1) s += __shfl_down_sync(0xffu, s, o);
        if (tid == 0) atomicAdd(&d_loss, (double)s);
    }
}

// ---------------- write result + restore zero-state invariant ----------------
__global__ void k_clean(float* out, double denom, int n) {
    int i = blockIdx.x * blockDim.x + threadIdx.x;
    if (i == 0) {
        out[0] = (float)(d_loss / denom);
        d_loss = 0.0;
        d_scan_tix = 0;
    }
    if (i < 128) d_scan_state[i] = 0ULL;
    if (i < n) { d_cnt[i] = 0; d_cur[i] = 0; }
}

// ---------------- launch ----------------
extern "C" void kernel_launch(void* const* d_in, const int* in_sizes, int n_in,
                              void* d_out, int out_size) {
    const float* nfeats = (const float*)d_in[0];
    const float* efeats = (const float*)d_in[1];
    const int*   src    = (const int*)d_in[2];
    const int*   dst    = (const int*)d_in[3];
    const int*   perm   = (const int*)d_in[4];
    const float* Wm0 = (const float*)d_in[5];
    const float* bm0 = (const float*)d_in[6];
    const float* Wa0 = (const float*)d_in[7];
    const float* ba0 = (const float*)d_in[8];
    const float* Wm1 = (const float*)d_in[9];
    const float* bm1 = (const float*)d_in[10];
    const float* Wa1 = (const float*)d_in[11];
    const float* ba1 = (const float*)d_in[12];

    int n = in_sizes[0] / 64;
    int E = in_sizes[2];
    int nb = (n + 1023) / 1024;

    cudaFuncSetAttribute(k_l0, cudaFuncAttributeMaxDynamicSharedMemorySize, GEMM_SMEM);
    cudaFuncSetAttribute(k_l1, cudaFuncAttributeMaxDynamicSharedMemorySize, GEMM_SMEM);

    int gw = (n * 32 + 255) / 256;  // one warp per node
    int gl = (n + 127) / 128;       // 128 nodes per tile

    k_hist   <<<(E + 255) / 256, 256>>>(dst, E);                            // 1
    k_scan   <<<nb, 1024>>>(n, E, nb);                                      // 2
    k_scatter<<<(E + 255) / 256, 256>>>(src, dst, perm, nfeats, E, n);      // 3 (+ nf cvt)
    k_agg3   <<<gw, 256>>>(efeats, n);                                      // 4 <- profiled
    k_fold2  <<<2, 256>>>(Wm0, bm0, Wa0, Wm1, bm1, Wa1);                    // 5
    k_l0     <<<gl, 256, GEMM_SMEM>>>(ba0, n);                              // 6
    k_aggh2  <<<gw, 256>>>(n);                                              // 7
    {
        dim3 grid(gl, 2);
        k_l1 <<<grid, 256, GEMM_SMEM>>>(ba1, n);                            // 8
    }
    k_clean  <<<(n + 255) / 256, 256>>>((float*)d_out, (double)n * 64.0, n); // 9
}

// round 16
// speedup vs baseline: 1.2746x; 1.0066x over previous
#include <cuda_runtime.h>
#include <cuda_bf16.h>
#include <math.h>
#include <cstdint>

#define NN 100000
#define EE 1000000

// ---------------- device scratch (zero-initialized at load; k_clean restores) ----------------
__device__ int    d_cnt[NN];
__device__ int    d_off[NN + 1];
__device__ int    d_cur[NN];
__device__ int    d_scan_tix;
__device__ unsigned long long d_scan_state[128];
__device__ int4   d_adj[EE];                    // {ssrc, eid, pid, 0}
__device__ __nv_bfloat16 d_nfb [(size_t)NN * 64];   // bf16 copy of nfeats (l0 staging only)
__device__ __nv_bfloat16 d_hagg0[(size_t)NN * 64];
__device__ __nv_bfloat16 d_efp [(size_t)NN * 64];
__device__ __nv_bfloat16 d_efn [(size_t)NN * 64];
__device__ __nv_bfloat16 d_h1p [(size_t)NN * 64];
__device__ __nv_bfloat16 d_h1n [(size_t)NN * 64];
__device__ __nv_bfloat16 d_hp  [(size_t)NN * 64];
__device__ __nv_bfloat16 d_hn  [(size_t)NN * 64];
// folded W in tf32, stored in exact mma B-fragment order
__device__ float  d_Wf[2][3 * 8 * 8 * 64];
__device__ float  d_cv[2][64];
__device__ double d_loss;

// ---------------- helpers ----------------
__device__ __forceinline__ float tf32r(float x) {
    uint32_t r; asm("cvt.rna.tf32.f32 %0, %1;" : "=r"(r) : "f"(x));
    return __uint_as_float(r);
}
__device__ __forceinline__ void mma_tf32(float* c, uint32_t a0, uint32_t a1, uint32_t a2, uint32_t a3,
                                         uint32_t b0, uint32_t b1) {
    asm volatile("mma.sync.aligned.m16n8k8.row.col.f32.tf32.tf32.f32 "
                 "{%0,%1,%2,%3}, {%4,%5,%6,%7}, {%8,%9}, {%0,%1,%2,%3};"
                 : "+f"(c[0]), "+f"(c[1]), "+f"(c[2]), "+f"(c[3])
                 : "r"(a0), "r"(a1), "r"(a2), "r"(a3), "r"(b0), "r"(b1));
}
__device__ __forceinline__ uint32_t bf2(float x, float y) {
    uint32_t r; asm("cvt.rn.satfinite.bf16x2.f32 %0, %1, %2;" : "=r"(r) : "f"(y), "f"(x)); return r;
}
__device__ __forceinline__ float2 bf2f(uint32_t v) {
    __nv_bfloat162 h = *reinterpret_cast<__nv_bfloat162*>(&v);
    return __bfloat1622float2(h);
}
__device__ __forceinline__ uint32_t hadd2(uint32_t a, uint32_t b) {
    uint32_t r; asm("add.rn.bf16x2 %0, %1, %2;" : "=r"(r) : "r"(a), "r"(b)); return r;
}

// ---------------- CSR build ----------------
__global__ void k_hist(const int* __restrict__ dst, int E) {
    int e = blockIdx.x * blockDim.x + threadIdx.x;
    if (e < E) atomicAdd(&d_cnt[dst[e]], 1);
}

__global__ void k_scan(int n, int E, int nb) {
    __shared__ int ws[32];
    __shared__ int s_bid;
    __shared__ int s_pref;
    if (threadIdx.x == 0) s_bid = atomicAdd(&d_scan_tix, 1);
    __syncthreads();
    int bid = s_bid;
    int i = bid * 1024 + threadIdx.x;
    int lane = threadIdx.x & 31, wid = threadIdx.x >> 5;
    int v = (i < n) ? d_cnt[i] : 0;
    int x = v;
    #pragma unroll
    for (int o = 1; o < 32; o <<= 1) { int y = __shfl_up_sync(~0u, x, o); if (lane >= o) x += y; }
    if (lane == 31) ws[wid] = x;
    __syncthreads();
    if (wid == 0) {
        int w = ws[lane];
        #pragma unroll
        for (int o = 1; o < 32; o <<= 1) { int y = __shfl_up_sync(~0u, w, o); if (lane >= o) w += y; }
        ws[lane] = w;
    }
    __syncthreads();
    int incl = x + (wid > 0 ? ws[wid - 1] : 0);
    int total = ws[31];
    if (threadIdx.x == 0) {
        if (bid == 0) {
            atomicExch(&d_scan_state[0], (2ULL << 32) | (unsigned)total);
            s_pref = 0;
        } else {
            atomicExch(&d_scan_state[bid], (1ULL << 32) | (unsigned)total);
            int pref = 0;
            for (int j = bid - 1; j >= 0; --j) {
                unsigned long long st;
                do { st = atomicAdd(&d_scan_state[j], 0ULL); } while (!(st >> 32));
                pref += (int)(unsigned)st;
                if ((st >> 32) == 2ULL) break;
            }
            atomicExch(&d_scan_state[bid], (2ULL << 32) | (unsigned)(pref + total));
            s_pref = pref;
        }
    }
    __syncthreads();
    int pref = s_pref;
    if (i < n) d_off[i] = pref + incl - v;
    if (bid == nb - 1 && threadIdx.x == 0) d_off[n] = E;
}

// k_scatter: CSR scatter + nfeats->bf16 conversion (small, hides under scatter latency)
__global__ void __launch_bounds__(256) k_scatter(const int* __restrict__ src,
                                                 const int* __restrict__ dst,
                                                 const int* __restrict__ perm,
                                                 const float* __restrict__ nf,
                                                 int E, int n) {
    int i = blockIdx.x * blockDim.x + threadIdx.x;
    int nth = gridDim.x * blockDim.x;
    if (i < E) {
        int d = dst[i];
        int p = d_off[d] + atomicAdd(&d_cur[d], 1);
        d_adj[p] = make_int4(src[i], i, perm[i], 0);
    }
    const float4* nfi = reinterpret_cast<const float4*>(nf);
    uint4* nfo = reinterpret_cast<uint4*>(d_nfb);
    int totn = n * 8;
    for (int t = i; t < totn; t += nth) {
        float4 a = __ldg(nfi + 2 * t);
        float4 b = __ldg(nfi + 2 * t + 1);
        nfo[t] = make_uint4(bf2(a.x, a.y), bf2(a.z, a.w), bf2(b.x, b.y), bf2(b.z, b.w));
    }
}

// ---------------- fused first-stage aggregation (R9 shape: all-fp32 gathers) ----------------
__global__ void __launch_bounds__(256) k_agg3(const float* __restrict__ nf,
                                              const float* __restrict__ ef, int n) {
    int gw = (blockIdx.x * blockDim.x + threadIdx.x) >> 5;
    int lane = threadIdx.x & 31;
    if (gw >= n) return;
    int beg = d_off[gw], end = d_off[gw + 1];
    const float2* nf2 = (const float2*)nf;
    const float2* ef2 = (const float2*)ef;
    float2 ah = make_float2(0.f, 0.f), ap = ah, an = ah;
    int k = beg;
    for (; k + 4 <= end; k += 4) {
        int4 a0 = __ldg(&d_adj[k]);
        int4 a1 = __ldg(&d_adj[k + 1]);
        int4 a2 = __ldg(&d_adj[k + 2]);
        int4 a3 = __ldg(&d_adj[k + 3]);
        float2 h0 = __ldg(nf2 + ((size_t)a0.x * 32 + lane));
        float2 p0 = __ldg(ef2 + ((size_t)a0.y * 32 + lane));
        float2 q0 = __ldg(ef2 + ((size_t)a0.z * 32 + lane));
        float2 h1 = __ldg(nf2 + ((size_t)a1.x * 32 + lane));
        float2 p1 = __ldg(ef2 + ((size_t)a1.y * 32 + lane));
        float2 q1 = __ldg(ef2 + ((size_t)a1.z * 32 + lane));
        float2 h2 = __ldg(nf2 + ((size_t)a2.x * 32 + lane));
        float2 p2 = __ldg(ef2 + ((size_t)a2.y * 32 + lane));
        float2 q2 = __ldg(ef2 + ((size_t)a2.z * 32 + lane));
        float2 h3 = __ldg(nf2 + ((size_t)a3.x * 32 + lane));
        float2 p3 = __ldg(ef2 + ((size_t)a3.y * 32 + lane));
        float2 q3 = __ldg(ef2 + ((size_t)a3.z * 32 + lane));
        ah.x += (h0.x + h1.x) + (h2.x + h3.x);
        ah.y += (h0.y + h1.y) + (h2.y + h3.y);
        ap.x += (p0.x + p1.x) + (p2.x + p3.x);
        ap.y += (p0.y + p1.y) + (p2.y + p3.y);
        an.x += (q0.x + q1.x) + (q2.x + q3.x);
        an.y += (q0.y + q1.y) + (q2.y + q3.y);
    }
    for (; k < end; ++k) {
        int4 a = __ldg(&d_adj[k]);
        float2 h = __ldg(nf2 + ((size_t)a.x * 32 + lane));
        float2 p = __ldg(ef2 + ((size_t)a.y * 32 + lane));
        float2 q = __ldg(ef2 + ((size_t)a.z * 32 + lane));
        ah.x += h.x; ah.y += h.y;
        ap.x += p.x; ap.y += p.y;
        an.x += q.x; an.y += q.y;
    }
    float inv = 1.f / fmaxf((float)(end - beg), 1.f);
    reinterpret_cast<uint32_t*>(d_hagg0)[(size_t)gw * 32 + lane] = bf2(ah.x * inv, ah.y * inv);
    reinterpret_cast<uint32_t*>(d_efp)  [(size_t)gw * 32 + lane] = bf2(ap.x * inv, ap.y * inv);
    reinterpret_cast<uint32_t*>(d_efn)  [(size_t)gw * 32 + lane] = bf2(an.x * inv, an.y * inv);
}

// ---------------- second-stage aggregation: hp + hn (bf16, HADD2 tree) ----------------
__global__ void __launch_bounds__(256) k_aggh2(int n) {
    int gw = (blockIdx.x * blockDim.x + threadIdx.x) >> 5;
    int lane = threadIdx.x & 31;
    if (gw >= n) return;
    int beg = d_off[gw], end = d_off[gw + 1];
    const uint32_t* fa = reinterpret_cast<const uint32_t*>(d_h1p);
    const uint32_t* fb = reinterpret_cast<const uint32_t*>(d_h1n);
    const int* adjs = reinterpret_cast<const int*>(d_adj);
    float2 aa = make_float2(0.f, 0.f), ab = aa;
    int k = beg;
    for (; k + 4 <= end; k += 4) {
        int s0 = __ldg(adjs + 4 * k);
        int s1 = __ldg(adjs + 4 * (k + 1));
        int s2 = __ldg(adjs + 4 * (k + 2));
        int s3 = __ldg(adjs + 4 * (k + 3));
        uint32_t v0 = __ldg(fa + ((size_t)s0 * 32 + lane));
        uint32_t u0 = __ldg(fb + ((size_t)s0 * 32 + lane));
        uint32_t v1 = __ldg(fa + ((size_t)s1 * 32 + lane));
        uint32_t u1 = __ldg(fb + ((size_t)s1 * 32 + lane));
        uint32_t v2 = __ldg(fa + ((size_t)s2 * 32 + lane));
        uint32_t u2 = __ldg(fb + ((size_t)s2 * 32 + lane));
        uint32_t v3 = __ldg(fa + ((size_t)s3 * 32 + lane));
        uint32_t u3 = __ldg(fb + ((size_t)s3 * 32 + lane));
        float2 t;
        t = bf2f(hadd2(hadd2(v0, v1), hadd2(v2, v3))); aa.x += t.x; aa.y += t.y;
        t = bf2f(hadd2(hadd2(u0, u1), hadd2(u2, u3))); ab.x += t.x; ab.y += t.y;
    }
    for (; k < end; ++k) {
        int s = __ldg(adjs + 4 * k);
        float2 t;
        t = bf2f(__ldg(fa + ((size_t)s * 32 + lane))); aa.x += t.x; aa.y += t.y;
        t = bf2f(__ldg(fb + ((size_t)s * 32 + lane))); ab.x += t.x; ab.y += t.y;
    }
    float inv = 1.f / fmaxf((float)(end - beg), 1.f);
    reinterpret_cast<uint32_t*>(d_hp)[(size_t)gw * 32 + lane] = bf2(aa.x * inv, aa.y * inv);
    reinterpret_cast<uint32_t*>(d_hn)[(size_t)gw * 32 + lane] = bf2(ab.x * inv, ab.y * inv);
}

// ---------------- fold Wmsg into Wapply -> tf32 B-fragment layout ----------------
__global__ void k_fold2(const float* __restrict__ Wm0, const float* __restrict__ bm0,
                        const float* __restrict__ Wa0,
                        const float* __restrict__ Wm1, const float* __restrict__ bm1,
                        const float* __restrict__ Wa1) {
    int layer = blockIdx.x;
    const float* Wmsg = layer ? Wm1 : Wm0;
    const float* bmsg = layer ? bm1 : bm0;
    const float* Wap  = layer ? Wa1 : Wa0;
    __shared__ float Wn[64][64];
    __shared__ float bm[64];
    int tid = threadIdx.x;
    for (int idx = tid; idx < 64 * 64; idx += 256) {
        int j = idx >> 6, t = idx & 63;
        Wn[t][j] = Wap[j * 128 + 64 + t];
    }
    if (tid < 64) bm[tid] = bmsg[tid];
    __syncthreads();
    for (int idx = tid; idx < 192 * 64; idx += 256) {
        int k = idx >> 6, j = idx & 63;
        float r;
        if (k < 64) {
            r = Wap[j * 128 + k];
        } else {
            int col = k - 64;
            float a = 0.f;
            #pragma unroll
            for (int t = 0; t < 64; ++t) a += Wmsg[t * 128 + col] * Wn[t][j];
            r = a;
        }
        int panel = k >> 6, kk = k & 63;
        int s = kk >> 3, krem = kk & 7;
        int slot = krem >> 2, kq = krem & 3;
        int t = ((j & 7) << 2) | kq;
        int nb = j >> 3;
        int o = ((panel * 8 + s) * 8 + nb) * 64 + t * 2 + slot;
        d_Wf[layer][o] = tf32r(r);
    }
    for (int j = tid; j < 64; j += 256) {
        float a = 0.f;
        #pragma unroll
        for (int t = 0; t < 64; ++t) a += bm[t] * Wn[t][j];
        d_cv[layer][j] = a;
    }
}

// ---------------- mma GEMM building blocks ----------------
#define XST 68
#define SM_X 0
#define SM_W (128 * XST)                 // 3 panels of 4096 floats
#define SM_B (SM_W + 3 * 4096)
#define SM_C (SM_B + 64)
#define SM_TOTF (SM_C + 64)
#define GEMM_SMEM (SM_TOTF * 4)

__device__ __forceinline__ void pf_load(uint4* pf, const __nv_bfloat16* __restrict__ S,
                                        int node0, int n, int tid) {
    #pragma unroll
    for (int it = 0; it < 4; ++it) {
        int t = tid + it * 256;
        int r = t >> 3, u4 = t & 7;
        int nd = node0 + r;
        pf[it] = make_uint4(0u, 0u, 0u, 0u);
        if (nd < n) pf[it] = __ldg(reinterpret_cast<const uint4*>(S) + (size_t)nd * 8 + u4);
    }
}
__device__ __forceinline__ void pf_store(float* __restrict__ Xs, const uint4* pf, int tid) {
    #pragma unroll
    for (int it = 0; it < 4; ++it) {
        int t = tid + it * 256;
        int r = t >> 3, u4 = t & 7;
        float2 f0 = bf2f(pf[it].x), f1 = bf2f(pf[it].y), f2 = bf2f(pf[it].z), f3 = bf2f(pf[it].w);
        *reinterpret_cast<float4*>(Xs + r * XST + u4 * 8)     = make_float4(f0.x, f0.y, f1.x, f1.y);
        *reinterpret_cast<float4*>(Xs + r * XST + u4 * 8 + 4) = make_float4(f2.x, f2.y, f3.x, f3.y);
    }
}
__device__ __forceinline__ void stage_w_all(float* __restrict__ Wp, const float* __restrict__ Wg, int tid) {
    #pragma unroll
    for (int it = 0; it < 12; ++it) {
        int t = tid + it * 256;
        reinterpret_cast<float4*>(Wp)[t] = __ldg(reinterpret_cast<const float4*>(Wg) + t);
    }
}
__device__ __forceinline__ void mma_phase(const float* __restrict__ Xs, const float* __restrict__ Wp,
                                          float* acc, int r0w, int lane) {
    int ar = r0w + (lane >> 2);
    #pragma unroll
    for (int s = 0; s < 8; ++s) {
        int ac = s * 8 + (lane & 3);
        uint32_t a0 = __float_as_uint(Xs[ar * XST + ac]);
        uint32_t a1 = __float_as_uint(Xs[(ar + 8) * XST + ac]);
        uint32_t a2 = __float_as_uint(Xs[ar * XST + ac + 4]);
        uint32_t a3 = __float_as_uint(Xs[(ar + 8) * XST + ac + 4]);
        #pragma unroll
        for (int nb = 0; nb < 8; ++nb) {
            float2 b = *reinterpret_cast<const float2*>(Wp + (s * 8 + nb) * 64 + lane * 2);
            mma_tf32(acc + nb * 4, a0, a1, a2, a3, __float_as_uint(b.x), __float_as_uint(b.y));
        }
    }
}

__device__ __forceinline__ float indf(int nd, int n) {
    return (nd < n && d_off[nd + 1] > d_off[nd]) ? 1.f : 0.f;
}

__device__ __forceinline__ void epi0(const float* acc, const float* __restrict__ sb,
                                     const float* __restrict__ sc, __nv_bfloat16* __restrict__ out,
                                     int node0, int r0w, int lane, int n) {
    int rA = node0 + r0w + (lane >> 2);
    int rB = rA + 8;
    float indA = indf(rA, n), indB = indf(rB, n);
    uint32_t* o32 = reinterpret_cast<uint32_t*>(out);
    #pragma unroll
    for (int nb = 0; nb < 8; ++nb) {
        int cc = nb * 8 + (lane & 3) * 2;
        float xA0 = fmaxf(acc[nb*4+0] + sb[cc]   + indA * sc[cc],   0.f);
        float xA1 = fmaxf(acc[nb*4+1] + sb[cc+1] + indA * sc[cc+1], 0.f);
        float xB0 = fmaxf(acc[nb*4+2] + sb[cc]   + indB * sc[cc],   0.f);
        float xB1 = fmaxf(acc[nb*4+3] + sb[cc+1] + indB * sc[cc+1], 0.f);
        if (rA < n) o32[(size_t)rA * 32 + (cc >> 1)] = bf2(xA0, xA1);
        if (rB < n) o32[(size_t)rB * 32 + (cc >> 1)] = bf2(xB0, xB1);
    }
}

// ---------------- layer 0 (software-pipelined staging) ----------------
__global__ void __launch_bounds__(256) k_l0(const float* __restrict__ bap, int n)
{
    extern __shared__ float sm[];
    float* Xs = sm + SM_X;
    float* Wp = sm + SM_W;
    float* sb = sm + SM_B;
    float* sc = sm + SM_C;
    int tid = threadIdx.x, wid = tid >> 5, lane = tid & 31;
    int node0 = blockIdx.x * 128;
    int r0w = wid * 16;
    if (tid < 64) { sb[tid] = bap[tid]; sc[tid] = d_cv[0][tid]; }
    stage_w_all(Wp, d_Wf[0], tid);

    float acc[32], accB[32];
    #pragma unroll
    for (int i = 0; i < 32; ++i) acc[i] = 0.f;

    uint4 pf[4];
    pf_load(pf, d_nfb, node0, n, tid);
    __syncthreads();
    pf_store(Xs, pf, tid);
    __syncthreads();
    pf_load(pf, d_hagg0, node0, n, tid);     // prefetch p1
    mma_phase(Xs, Wp, acc, r0w, lane);       // p0
    __syncthreads();
    pf_store(Xs, pf, tid);
    __syncthreads();
    pf_load(pf, d_efp, node0, n, tid);       // prefetch p2
    mma_phase(Xs, Wp + 4096, acc, r0w, lane);// p1
    #pragma unroll
    for (int i = 0; i < 32; ++i) accB[i] = acc[i];
    __syncthreads();
    pf_store(Xs, pf, tid);
    __syncthreads();
    pf_load(pf, d_efn, node0, n, tid);       // prefetch p3
    mma_phase(Xs, Wp + 8192, acc, r0w, lane);// p2
    epi0(acc, sb, sc, d_h1p, node0, r0w, lane, n);
    __syncthreads();
    pf_store(Xs, pf, tid);
    __syncthreads();
    #pragma unroll
    for (int i = 0; i < 32; ++i) acc[i] = accB[i];
    mma_phase(Xs, Wp + 8192, acc, r0w, lane);// p3
    epi0(acc, sb, sc, d_h1n, node0, r0w, lane, n);
}

// ---------------- layer 1 (software-pipelined, fused BCE) ----------------
__global__ void __launch_bounds__(256) k_l1(const float* __restrict__ bap, int n)
{
    extern __shared__ float sm[];
    float* Xs = sm + SM_X;
    float* Wp = sm + SM_W;
    float* sb = sm + SM_B;
    float* sc = sm + SM_C;
    __shared__ float wred[8];
    int tid = threadIdx.x, wid = tid >> 5, lane = tid & 31;
    int node0 = blockIdx.x * 128;
    int r0w = wid * 16;
    int view = blockIdx.y;
    if (tid < 64) { sb[tid] = bap[tid]; sc[tid] = d_cv[1][tid]; }
    stage_w_all(Wp, d_Wf[1], tid);

    const __nv_bfloat16* S0 = view ? d_h1n : d_h1p;
    const __nv_bfloat16* S1 = view ? d_hn  : d_hp;
    const __nv_bfloat16* S2 = view ? d_efn : d_efp;

    float acc[32];
    #pragma unroll
    for (int i = 0; i < 32; ++i) acc[i] = 0.f;

    uint4 pf[4];
    pf_load(pf, S0, node0, n, tid);
    __syncthreads();
    pf_store(Xs, pf, tid);
    __syncthreads();
    pf_load(pf, S1, node0, n, tid);
    mma_phase(Xs, Wp, acc, r0w, lane);
    __syncthreads();
    pf_store(Xs, pf, tid);
    __syncthreads();
    pf_load(pf, S2, node0, n, tid);
    mma_phase(Xs, Wp + 4096, acc, r0w, lane);
    __syncthreads();
    pf_store(Xs, pf, tid);
    __syncthreads();
    mma_phase(Xs, Wp + 8192, acc, r0w, lane);

    int rA = node0 + r0w + (lane >> 2);
    int rB = rA + 8;
    float indA = indf(rA, n), indB = indf(rB, n);
    float lsum = 0.f;
    #pragma unroll
    for (int nb = 0; nb < 8; ++nb) {
        int cc = nb * 8 + (lane & 3) * 2;
        float xA0 = fmaxf(acc[nb*4+0] + sb[cc]   + indA * sc[cc],   0.f);
        float xA1 = fmaxf(acc[nb*4+1] + sb[cc+1] + indA * sc[cc+1], 0.f);
        float xB0 = fmaxf(acc[nb*4+2] + sb[cc]   + indB * sc[cc],   0.f);
        float xB1 = fmaxf(acc[nb*4+3] + sb[cc+1] + indB * sc[cc+1], 0.f);
        if (rA < n) {
            float t0 = log1pf(expf(-xA0)), t1 = log1pf(expf(-xA1));
            lsum += view ? (xA0 + t0 + xA1 + t1) : (t0 + t1);
        }
        if (rB < n) {
            float t0 = log1pf(expf(-xB0)), t1 = log1pf(expf(-xB1));
            lsum += view ? (xB0 + t0 + xB1 + t1) : (t0 + t1);
        }
    }
    #pragma unroll
    for (int o = 16; o; o >>= 1) lsum += __shfl_down_sync(~0u, lsum, o);
    if (lane == 0) wred[wid] = lsum;
    __syncthreads();
    if (tid < 8) {
        float s = wred[tid];
        #pragma unroll
        for (int o = 4; o; o >>= 1) s += __shfl_down_sync(0xffu, s, o);
        if (tid == 0) atomicAdd(&d_loss, (double)s);
    }
}

// ---------------- write result + restore zero-state invariant ----------------
__global__ void k_clean(float* out, double denom, int n) {
    int i = blockIdx.x * blockDim.x + threadIdx.x;
    if (i == 0) {
        out[0] = (float)(d_loss / denom);
        d_loss = 0.0;
        d_scan_tix = 0;
    }
    if (i < 128) d_scan_state[i] = 0ULL;
    if (i < n) { d_cnt[i] = 0; d_cur[i] = 0; }
}

// ---------------- launch ----------------
extern "C" void kernel_launch(void* const* d_in, const int* in_sizes, int n_in,
                              void* d_out, int out_size) {
    const float* nfeats = (const float*)d_in[0];
    const float* efeats = (const float*)d_in[1];
    const int*   src    = (const int*)d_in[2];
    const int*   dst    = (const int*)d_in[3];
    const int*   perm   = (const int*)d_in[4];
    const float* Wm0 = (const float*)d_in[5];
    const float* bm0 = (const float*)d_in[6];
    const float* Wa0 = (const float*)d_in[7];
    const float* ba0 = (const float*)d_in[8];
    const float* Wm1 = (const float*)d_in[9];
    const float* bm1 = (const float*)d_in[10];
    const float* Wa1 = (const float*)d_in[11];
    const float* ba1 = (const float*)d_in[12];

    int n = in_sizes[0] / 64;
    int E = in_sizes[2];
    int nb = (n + 1023) / 1024;

    cudaFuncSetAttribute(k_l0, cudaFuncAttributeMaxDynamicSharedMemorySize, GEMM_SMEM);
    cudaFuncSetAttribute(k_l1, cudaFuncAttributeMaxDynamicSharedMemorySize, GEMM_SMEM);

    int gw = (n * 32 + 255) / 256;  // one warp per node
    int gl = (n + 127) / 128;       // 128 nodes per tile

    k_hist   <<<(E + 255) / 256, 256>>>(dst, E);                            // 1
    k_scan   <<<nb, 1024>>>(n, E, nb);                                      // 2
    k_scatter<<<(E + 255) / 256, 256>>>(src, dst, perm, nfeats, E, n);      // 3 (+ nf cvt)
    k_agg3   <<<gw, 256>>>(nfeats, efeats, n);                              // 4 <- profiled
    k_fold2  <<<2, 256>>>(Wm0, bm0, Wa0, Wm1, bm1, Wa1);                    // 5
    k_l0     <<<gl, 256, GEMM_SMEM>>>(ba0, n);                              // 6
    k_aggh2  <<<gw, 256>>>(n);                                              // 7
    {
        dim3 grid(gl, 2);
        k_l1 <<<grid, 256, GEMM_SMEM>>>(ba1, n);                            // 8
    }
    k_clean  <<<(n + 255) / 256, 256>>>((float*)d_out, (double)n * 64.0, n); // 9
}

// round 17
// speedup vs baseline: 1.5244x; 1.1960x over previous
#include <cuda_runtime.h>
#include <cuda_bf16.h>
#include <math.h>
#include <cstdint>

#define NN 100000
#define EE 1000000

// ---------------- device scratch (zero-initialized at load; kernels restore) ----------------
__device__ int    d_cnt[NN];
__device__ int    d_off[NN + 1];
__device__ int    d_cur[NN];
__device__ int    d_scan_tix;
__device__ unsigned long long d_scan_state[128];
__device__ int4   d_adj[EE];                    // {ssrc, eid, pid, 0}
__device__ float  d_base[(size_t)NN * 64];      // nfeats @ W0[panel0] (fp32)
__device__ __nv_bfloat16 d_hagg0[(size_t)NN * 64];
__device__ __nv_bfloat16 d_efp [(size_t)NN * 64];
__device__ __nv_bfloat16 d_efn [(size_t)NN * 64];
__device__ __nv_bfloat16 d_h1p [(size_t)NN * 64];
__device__ __nv_bfloat16 d_h1n [(size_t)NN * 64];
__device__ __nv_bfloat16 d_hp  [(size_t)NN * 64];
__device__ __nv_bfloat16 d_hn  [(size_t)NN * 64];
// folded W in tf32, stored in exact mma B-fragment order
__device__ float  d_Wf[2][3 * 8 * 8 * 64];
__device__ float  d_cv[2][64];
__device__ double d_loss;

// ---------------- helpers ----------------
__device__ __forceinline__ float tf32r(float x) {
    uint32_t r; asm("cvt.rna.tf32.f32 %0, %1;" : "=r"(r) : "f"(x));
    return __uint_as_float(r);
}
__device__ __forceinline__ void mma_tf32(float* c, uint32_t a0, uint32_t a1, uint32_t a2, uint32_t a3,
                                         uint32_t b0, uint32_t b1) {
    asm volatile("mma.sync.aligned.m16n8k8.row.col.f32.tf32.tf32.f32 "
                 "{%0,%1,%2,%3}, {%4,%5,%6,%7}, {%8,%9}, {%0,%1,%2,%3};"
                 : "+f"(c[0]), "+f"(c[1]), "+f"(c[2]), "+f"(c[3])
                 : "r"(a0), "r"(a1), "r"(a2), "r"(a3), "r"(b0), "r"(b1));
}
__device__ __forceinline__ uint32_t bf2(float x, float y) {
    uint32_t r; asm("cvt.rn.satfinite.bf16x2.f32 %0, %1, %2;" : "=r"(r) : "f"(y), "f"(x)); return r;
}
__device__ __forceinline__ float2 bf2f(uint32_t v) {
    __nv_bfloat162 h = *reinterpret_cast<__nv_bfloat162*>(&v);
    return __bfloat1622float2(h);
}
__device__ __forceinline__ uint32_t hadd2(uint32_t a, uint32_t b) {
    uint32_t r; asm("add.rn.bf16x2 %0, %1, %2;" : "=r"(r) : "r"(a), "r"(b)); return r;
}

// ---------------- CSR build ----------------
__global__ void k_hist(const int* __restrict__ dst, int E) {
    int e = blockIdx.x * blockDim.x + threadIdx.x;
    if (e < E) atomicAdd(&d_cnt[dst[e]], 1);
}

__global__ void k_scan(int n, int E, int nb) {
    __shared__ int ws[32];
    __shared__ int s_bid;
    __shared__ int s_pref;
    if (threadIdx.x == 0) s_bid = atomicAdd(&d_scan_tix, 1);
    __syncthreads();
    int bid = s_bid;
    int i = bid * 1024 + threadIdx.x;
    int lane = threadIdx.x & 31, wid = threadIdx.x >> 5;
    int v = (i < n) ? d_cnt[i] : 0;
    int x = v;
    #pragma unroll
    for (int o = 1; o < 32; o <<= 1) { int y = __shfl_up_sync(~0u, x, o); if (lane >= o) x += y; }
    if (lane == 31) ws[wid] = x;
    __syncthreads();
    if (wid == 0) {
        int w = ws[lane];
        #pragma unroll
        for (int o = 1; o < 32; o <<= 1) { int y = __shfl_up_sync(~0u, w, o); if (lane >= o) w += y; }
        ws[lane] = w;
    }
    __syncthreads();
    int incl = x + (wid > 0 ? ws[wid - 1] : 0);
    int total = ws[31];
    if (threadIdx.x == 0) {
        if (bid == 0) {
            atomicExch(&d_scan_state[0], (2ULL << 32) | (unsigned)total);
            s_pref = 0;
        } else {
            atomicExch(&d_scan_state[bid], (1ULL << 32) | (unsigned)total);
            int pref = 0;
            for (int j = bid - 1; j >= 0; --j) {
                unsigned long long st;
                do { st = atomicAdd(&d_scan_state[j], 0ULL); } while (!(st >> 32));
                pref += (int)(unsigned)st;
                if ((st >> 32) == 2ULL) break;
            }
            atomicExch(&d_scan_state[bid], (2ULL << 32) | (unsigned)(pref + total));
            s_pref = pref;
        }
    }
    __syncthreads();
    int pref = s_pref;
    if (i < n) d_off[i] = pref + incl - v;
    if (bid == nb - 1 && threadIdx.x == 0) d_off[n] = E;
}

__global__ void __launch_bounds__(256) k_scatter(const int* __restrict__ src,
                                                 const int* __restrict__ dst,
                                                 const int* __restrict__ perm, int E) {
    int i = blockIdx.x * blockDim.x + threadIdx.x;
    if (i < E) {
        int d = dst[i];
        int p = d_off[d] + atomicAdd(&d_cur[d], 1);
        d_adj[p] = make_int4(src[i], i, perm[i], 0);
    }
}

// ---------------- fused first-stage aggregation (all-fp32 gathers) + cnt/cur cleanup ----------------
__global__ void __launch_bounds__(256) k_agg3(const float* __restrict__ nf,
                                              const float* __restrict__ ef, int n) {
    int gw = (blockIdx.x * blockDim.x + threadIdx.x) >> 5;
    int lane = threadIdx.x & 31;
    if (gw >= n) return;
    int beg = d_off[gw], end = d_off[gw + 1];
    const float2* nf2 = (const float2*)nf;
    const float2* ef2 = (const float2*)ef;
    float2 ah = make_float2(0.f, 0.f), ap = ah, an = ah;
    int k = beg;
    for (; k + 4 <= end; k += 4) {
        int4 a0 = __ldg(&d_adj[k]);
        int4 a1 = __ldg(&d_adj[k + 1]);
        int4 a2 = __ldg(&d_adj[k + 2]);
        int4 a3 = __ldg(&d_adj[k + 3]);
        float2 h0 = __ldg(nf2 + ((size_t)a0.x * 32 + lane));
        float2 p0 = __ldg(ef2 + ((size_t)a0.y * 32 + lane));
        float2 q0 = __ldg(ef2 + ((size_t)a0.z * 32 + lane));
        float2 h1 = __ldg(nf2 + ((size_t)a1.x * 32 + lane));
        float2 p1 = __ldg(ef2 + ((size_t)a1.y * 32 + lane));
        float2 q1 = __ldg(ef2 + ((size_t)a1.z * 32 + lane));
        float2 h2 = __ldg(nf2 + ((size_t)a2.x * 32 + lane));
        float2 p2 = __ldg(ef2 + ((size_t)a2.y * 32 + lane));
        float2 q2 = __ldg(ef2 + ((size_t)a2.z * 32 + lane));
        float2 h3 = __ldg(nf2 + ((size_t)a3.x * 32 + lane));
        float2 p3 = __ldg(ef2 + ((size_t)a3.y * 32 + lane));
        float2 q3 = __ldg(ef2 + ((size_t)a3.z * 32 + lane));
        ah.x += (h0.x + h1.x) + (h2.x + h3.x);
        ah.y += (h0.y + h1.y) + (h2.y + h3.y);
        ap.x += (p0.x + p1.x) + (p2.x + p3.x);
        ap.y += (p0.y + p1.y) + (p2.y + p3.y);
        an.x += (q0.x + q1.x) + (q2.x + q3.x);
        an.y += (q0.y + q1.y) + (q2.y + q3.y);
    }
    for (; k < end; ++k) {
        int4 a = __ldg(&d_adj[k]);
        float2 h = __ldg(nf2 + ((size_t)a.x * 32 + lane));
        float2 p = __ldg(ef2 + ((size_t)a.y * 32 + lane));
        float2 q = __ldg(ef2 + ((size_t)a.z * 32 + lane));
        ah.x += h.x; ah.y += h.y;
        ap.x += p.x; ap.y += p.y;
        an.x += q.x; an.y += q.y;
    }
    float inv = 1.f / fmaxf((float)(end - beg), 1.f);
    reinterpret_cast<uint32_t*>(d_hagg0)[(size_t)gw * 32 + lane] = bf2(ah.x * inv, ah.y * inv);
    reinterpret_cast<uint32_t*>(d_efp)  [(size_t)gw * 32 + lane] = bf2(ap.x * inv, ap.y * inv);
    reinterpret_cast<uint32_t*>(d_efn)  [(size_t)gw * 32 + lane] = bf2(an.x * inv, an.y * inv);
    if (lane == 0) { d_cnt[gw] = 0; d_cur[gw] = 0; }   // restore zero-state for next call
}

// ---------------- second-stage aggregation: hp + hn (bf16, HADD2 tree) ----------------
__global__ void __launch_bounds__(256) k_aggh2(int n) {
    int gw = (blockIdx.x * blockDim.x + threadIdx.x) >> 5;
    int lane = threadIdx.x & 31;
    if (gw >= n) return;
    int beg = d_off[gw], end = d_off[gw + 1];
    const uint32_t* fa = reinterpret_cast<const uint32_t*>(d_h1p);
    const uint32_t* fb = reinterpret_cast<const uint32_t*>(d_h1n);
    const int* adjs = reinterpret_cast<const int*>(d_adj);
    float2 aa = make_float2(0.f, 0.f), ab = aa;
    int k = beg;
    for (; k + 4 <= end; k += 4) {
        int s0 = __ldg(adjs + 4 * k);
        int s1 = __ldg(adjs + 4 * (k + 1));
        int s2 = __ldg(adjs + 4 * (k + 2));
        int s3 = __ldg(adjs + 4 * (k + 3));
        uint32_t v0 = __ldg(fa + ((size_t)s0 * 32 + lane));
        uint32_t u0 = __ldg(fb + ((size_t)s0 * 32 + lane));
        uint32_t v1 = __ldg(fa + ((size_t)s1 * 32 + lane));
        uint32_t u1 = __ldg(fb + ((size_t)s1 * 32 + lane));
        uint32_t v2 = __ldg(fa + ((size_t)s2 * 32 + lane));
        uint32_t u2 = __ldg(fb + ((size_t)s2 * 32 + lane));
        uint32_t v3 = __ldg(fa + ((size_t)s3 * 32 + lane));
        uint32_t u3 = __ldg(fb + ((size_t)s3 * 32 + lane));
        float2 t;
        t = bf2f(hadd2(hadd2(v0, v1), hadd2(v2, v3))); aa.x += t.x; aa.y += t.y;
        t = bf2f(hadd2(hadd2(u0, u1), hadd2(u2, u3))); ab.x += t.x; ab.y += t.y;
    }
    for (; k < end; ++k) {
        int s = __ldg(adjs + 4 * k);
        float2 t;
        t = bf2f(__ldg(fa + ((size_t)s * 32 + lane))); aa.x += t.x; aa.y += t.y;
        t = bf2f(__ldg(fb + ((size_t)s * 32 + lane))); ab.x += t.x; ab.y += t.y;
    }
    float inv = 1.f / fmaxf((float)(end - beg), 1.f);
    reinterpret_cast<uint32_t*>(d_hp)[(size_t)gw * 32 + lane] = bf2(aa.x * inv, aa.y * inv);
    reinterpret_cast<uint32_t*>(d_hn)[(size_t)gw * 32 + lane] = bf2(ab.x * inv, ab.y * inv);
}

// ---------------- fold Wmsg into Wapply -> tf32 B-fragment layout ----------------
__global__ void k_fold2(const float* __restrict__ Wm0, const float* __restrict__ bm0,
                        const float* __restrict__ Wa0,
                        const float* __restrict__ Wm1, const float* __restrict__ bm1,
                        const float* __restrict__ Wa1) {
    int layer = blockIdx.x;
    const float* Wmsg = layer ? Wm1 : Wm0;
    const float* bmsg = layer ? bm1 : bm0;
    const float* Wap  = layer ? Wa1 : Wa0;
    __shared__ float Wn[64][64];
    __shared__ float bm[64];
    int tid = threadIdx.x;
    for (int idx = tid; idx < 64 * 64; idx += 256) {
        int j = idx >> 6, t = idx & 63;
        Wn[t][j] = Wap[j * 128 + 64 + t];
    }
    if (tid < 64) bm[tid] = bmsg[tid];
    __syncthreads();
    for (int idx = tid; idx < 192 * 64; idx += 256) {
        int k = idx >> 6, j = idx & 63;
        float r;
        if (k < 64) {
            r = Wap[j * 128 + k];
        } else {
            int col = k - 64;
            float a = 0.f;
            #pragma unroll
            for (int t = 0; t < 64; ++t) a += Wmsg[t * 128 + col] * Wn[t][j];
            r = a;
        }
        int panel = k >> 6, kk = k & 63;
        int s = kk >> 3, krem = kk & 7;
        int slot = krem >> 2, kq = krem & 3;
        int t = ((j & 7) << 2) | kq;
        int nb = j >> 3;
        int o = ((panel * 8 + s) * 8 + nb) * 64 + t * 2 + slot;
        d_Wf[layer][o] = tf32r(r);
    }
    for (int j = tid; j < 64; j += 256) {
        float a = 0.f;
        #pragma unroll
        for (int t = 0; t < 64; ++t) a += bm[t] * Wn[t][j];
        d_cv[layer][j] = a;
    }
}

// ---------------- mma GEMM building blocks ----------------
#define XST 68
#define SM_X 0
#define L0_W (128 * XST)
#define L0_B (L0_W + 2 * 4096)
#define L0_C (L0_B + 64)
#define L0_SMEM ((L0_C + 64) * 4)
#define L1_W (128 * XST)
#define L1_B (L1_W + 3 * 4096)
#define L1_C (L1_B + 64)
#define L1_SMEM ((L1_C + 64) * 4)
#define BASE_SMEM ((128 * XST + 4096) * 4)

__device__ __forceinline__ void pf_load(uint4* pf, const __nv_bfloat16* __restrict__ S,
                                        int node0, int n, int tid) {
    #pragma unroll
    for (int it = 0; it < 4; ++it) {
        int t = tid + it * 256;
        int r = t >> 3, u4 = t & 7;
        int nd = node0 + r;
        pf[it] = make_uint4(0u, 0u, 0u, 0u);
        if (nd < n) pf[it] = __ldg(reinterpret_cast<const uint4*>(S) + (size_t)nd * 8 + u4);
    }
}
__device__ __forceinline__ void pf_store(float* __restrict__ Xs, const uint4* pf, int tid) {
    #pragma unroll
    for (int it = 0; it < 4; ++it) {
        int t = tid + it * 256;
        int r = t >> 3, u4 = t & 7;
        float2 f0 = bf2f(pf[it].x), f1 = bf2f(pf[it].y), f2 = bf2f(pf[it].z), f3 = bf2f(pf[it].w);
        *reinterpret_cast<float4*>(Xs + r * XST + u4 * 8)     = make_float4(f0.x, f0.y, f1.x, f1.y);
        *reinterpret_cast<float4*>(Xs + r * XST + u4 * 8 + 4) = make_float4(f2.x, f2.y, f3.x, f3.y);
    }
}
__device__ __forceinline__ void stage_f32(float* __restrict__ Xs, const float* __restrict__ S,
                                          int node0, int n, int tid) {
    #pragma unroll
    for (int it = 0; it < 8; ++it) {
        int t = tid + it * 256;
        int r = t >> 4, c4 = (t & 15) << 2;
        int nd = node0 + r;
        float4 v = make_float4(0.f, 0.f, 0.f, 0.f);
        if (nd < n) v = __ldg(reinterpret_cast<const float4*>(S) + (size_t)nd * 16 + (t & 15));
        v.x = tf32r(v.x); v.y = tf32r(v.y); v.z = tf32r(v.z); v.w = tf32r(v.w);
        *reinterpret_cast<float4*>(Xs + r * XST + c4) = v;
    }
}
__device__ __forceinline__ void stage_w_n(float* __restrict__ Wp, const float* __restrict__ Wg,
                                          int tid, int iters) {
    for (int it = 0; it < iters; ++it) {
        int t = tid + it * 256;
        reinterpret_cast<float4*>(Wp)[t] = __ldg(reinterpret_cast<const float4*>(Wg) + t);
    }
}
__device__ __forceinline__ void mma_phase(const float* __restrict__ Xs, const float* __restrict__ Wp,
                                          float* acc, int r0w, int lane) {
    int ar = r0w + (lane >> 2);
    #pragma unroll
    for (int s = 0; s < 8; ++s) {
        int ac = s * 8 + (lane & 3);
        uint32_t a0 = __float_as_uint(Xs[ar * XST + ac]);
        uint32_t a1 = __float_as_uint(Xs[(ar + 8) * XST + ac]);
        uint32_t a2 = __float_as_uint(Xs[ar * XST + ac + 4]);
        uint32_t a3 = __float_as_uint(Xs[(ar + 8) * XST + ac + 4]);
        #pragma unroll
        for (int nb = 0; nb < 8; ++nb) {
            float2 b = *reinterpret_cast<const float2*>(Wp + (s * 8 + nb) * 64 + lane * 2);
            mma_tf32(acc + nb * 4, a0, a1, a2, a3, __float_as_uint(b.x), __float_as_uint(b.y));
        }
    }
}

__device__ __forceinline__ float indf(int nd, int n) {
    return (nd < n && d_off[nd + 1] > d_off[nd]) ? 1.f : 0.f;
}

__device__ __forceinline__ void epi0(const float* acc, const float* __restrict__ sb,
                                     const float* __restrict__ sc, __nv_bfloat16* __restrict__ out,
                                     int node0, int r0w, int lane, int n) {
    int rA = node0 + r0w + (lane >> 2);
    int rB = rA + 8;
    float indA = indf(rA, n), indB = indf(rB, n);
    uint32_t* o32 = reinterpret_cast<uint32_t*>(out);
    #pragma unroll
    for (int nb = 0; nb < 8; ++nb) {
        int cc = nb * 8 + (lane & 3) * 2;
        float xA0 = fmaxf(acc[nb*4+0] + sb[cc]   + indA * sc[cc],   0.f);
        float xA1 = fmaxf(acc[nb*4+1] + sb[cc+1] + indA * sc[cc+1], 0.f);
        float xB0 = fmaxf(acc[nb*4+2] + sb[cc]   + indB * sc[cc],   0.f);
        float xB1 = fmaxf(acc[nb*4+3] + sb[cc+1] + indB * sc[cc+1], 0.f);
        if (rA < n) o32[(size_t)rA * 32 + (cc >> 1)] = bf2(xA0, xA1);
        if (rB < n) o32[(size_t)rB * 32 + (cc >> 1)] = bf2(xB0, xB1);
    }
}

// ---------------- base GEMM: d_base = nfeats @ W0[panel0] (runs on side stream) ----------------
__global__ void __launch_bounds__(256) k_base(const float* __restrict__ nfeats, int n) {
    extern __shared__ float sm[];
    float* Xs = sm + SM_X;
    float* Wp = sm + 128 * XST;
    int tid = threadIdx.x, wid = tid >> 5, lane = tid & 31;
    int node0 = blockIdx.x * 128;
    int r0w = wid * 16;

    stage_f32(Xs, nfeats, node0, n, tid);
    stage_w_n(Wp, d_Wf[0], tid, 4);
    __syncthreads();

    float acc[32];
    #pragma unroll
    for (int i = 0; i < 32; ++i) acc[i] = 0.f;
    mma_phase(Xs, Wp, acc, r0w, lane);

    int rA = node0 + r0w + (lane >> 2);
    int rB = rA + 8;
    #pragma unroll
    for (int nb = 0; nb < 8; ++nb) {
        int cc = nb * 8 + (lane & 3) * 2;
        if (rA < n) *reinterpret_cast<float2*>(d_base + (size_t)rA * 64 + cc) =
            make_float2(acc[nb*4+0], acc[nb*4+1]);
        if (rB < n) *reinterpret_cast<float2*>(d_base + (size_t)rB * 64 + cc) =
            make_float2(acc[nb*4+2], acc[nb*4+3]);
    }
}

// ---------------- layer 0: accB from d_base, 3 pipelined phases ----------------
__global__ void __launch_bounds__(256) k_l0(const float* __restrict__ bap, int n)
{
    extern __shared__ float sm[];
    float* Xs = sm + SM_X;
    float* Wp = sm + L0_W;
    float* sb = sm + L0_B;
    float* sc = sm + L0_C;
    int tid = threadIdx.x, wid = tid >> 5, lane = tid & 31;
    int node0 = blockIdx.x * 128;
    int r0w = wid * 16;
    if (tid < 64) { sb[tid] = bap[tid]; sc[tid] = d_cv[0][tid]; }
    stage_w_n(Wp, d_Wf[0] + 4096, tid, 8);   // panels 1,2

    int rA = node0 + r0w + (lane >> 2);
    int rB = rA + 8;
    float accB[32], acc[32];
    #pragma unroll
    for (int nb = 0; nb < 8; ++nb) {
        int cc = nb * 8 + (lane & 3) * 2;
        float2 vA = make_float2(0.f, 0.f), vB = vA;
        if (rA < n) vA = *reinterpret_cast<const float2*>(d_base + (size_t)rA * 64 + cc);
        if (rB < n) vB = *reinterpret_cast<const float2*>(d_base + (size_t)rB * 64 + cc);
        accB[nb*4+0] = vA.x; accB[nb*4+1] = vA.y;
        accB[nb*4+2] = vB.x; accB[nb*4+3] = vB.y;
    }

    uint4 pf[4];
    pf_load(pf, d_hagg0, node0, n, tid);
    __syncthreads();
    pf_store(Xs, pf, tid);
    __syncthreads();
    pf_load(pf, d_efp, node0, n, tid);        // prefetch p2
    mma_phase(Xs, Wp, accB, r0w, lane);       // p1: hagg0 (panel1)
    __syncthreads();
    pf_store(Xs, pf, tid);
    __syncthreads();
    pf_load(pf, d_efn, node0, n, tid);        // prefetch p3
    #pragma unroll
    for (int i = 0; i < 32; ++i) acc[i] = accB[i];
    mma_phase(Xs, Wp + 4096, acc, r0w, lane); // p2: efp (panel2)
    epi0(acc, sb, sc, d_h1p, node0, r0w, lane, n);
    __syncthreads();
    pf_store(Xs, pf, tid);
    __syncthreads();
    #pragma unroll
    for (int i = 0; i < 32; ++i) acc[i] = accB[i];
    mma_phase(Xs, Wp + 4096, acc, r0w, lane); // p3: efn (panel2)
    epi0(acc, sb, sc, d_h1n, node0, r0w, lane, n);
}

// ---------------- layer 1 (software-pipelined, fused BCE) ----------------
__global__ void __launch_bounds__(256) k_l1(const float* __restrict__ bap, int n)
{
    extern __shared__ float sm[];
    float* Xs = sm + SM_X;
    float* Wp = sm + L1_W;
    float* sb = sm + L1_B;
    float* sc = sm + L1_C;
    __shared__ float wred[8];
    int tid = threadIdx.x, wid = tid >> 5, lane = tid & 31;
    int node0 = blockIdx.x * 128;
    int r0w = wid * 16;
    int view = blockIdx.y;
    if (tid < 64) { sb[tid] = bap[tid]; sc[tid] = d_cv[1][tid]; }
    stage_w_n(Wp, d_Wf[1], tid, 12);

    const __nv_bfloat16* S0 = view ? d_h1n : d_h1p;
    const __nv_bfloat16* S1 = view ? d_hn  : d_hp;
    const __nv_bfloat16* S2 = view ? d_efn : d_efp;

    float acc[32];
    #pragma unroll
    for (int i = 0; i < 32; ++i) acc[i] = 0.f;

    uint4 pf[4];
    pf_load(pf, S0, node0, n, tid);
    __syncthreads();
    pf_store(Xs, pf, tid);
    __syncthreads();
    pf_load(pf, S1, node0, n, tid);
    mma_phase(Xs, Wp, acc, r0w, lane);
    __syncthreads();
    pf_store(Xs, pf, tid);
    __syncthreads();
    pf_load(pf, S2, node0, n, tid);
    mma_phase(Xs, Wp + 4096, acc, r0w, lane);
    __syncthreads();
    pf_store(Xs, pf, tid);
    __syncthreads();
    mma_phase(Xs, Wp + 8192, acc, r0w, lane);

    int rA = node0 + r0w + (lane >> 2);
    int rB = rA + 8;
    float indA = indf(rA, n), indB = indf(rB, n);
    float lsum = 0.f;
    #pragma unroll
    for (int nb = 0; nb < 8; ++nb) {
        int cc = nb * 8 + (lane & 3) * 2;
        float xA0 = fmaxf(acc[nb*4+0] + sb[cc]   + indA * sc[cc],   0.f);
        float xA1 = fmaxf(acc[nb*4+1] + sb[cc+1] + indA * sc[cc+1], 0.f);
        float xB0 = fmaxf(acc[nb*4+2] + sb[cc]   + indB * sc[cc],   0.f);
        float xB1 = fmaxf(acc[nb*4+3] + sb[cc+1] + indB * sc[cc+1], 0.f);
        if (rA < n) {
            float t0 = log1pf(expf(-xA0)), t1 = log1pf(expf(-xA1));
            lsum += view ? (xA0 + t0 + xA1 + t1) : (t0 + t1);
        }
        if (rB < n) {
            float t0 = log1pf(expf(-xB0)), t1 = log1pf(expf(-xB1));
            lsum += view ? (xB0 + t0 + xB1 + t1) : (t0 + t1);
        }
    }
    #pragma unroll
    for (int o = 16; o; o >>= 1) lsum += __shfl_down_sync(~0u, lsum, o);
    if (lane == 0) wred[wid] = lsum;
    __syncthreads();
    if (tid < 8) {
        float s = wred[tid];
        #pragma unroll
        for (int o = 4; o; o >>= 1) s += __shfl_down_sync(0xffu, s, o);
        if (tid == 0) atomicAdd(&d_loss, (double)s);
    }
}

// ---------------- write result + restore remaining zero-state ----------------
__global__ void k_clean(float* out, double denom) {
    int i = threadIdx.x;
    if (i == 0) {
        out[0] = (float)(d_loss / denom);
        d_loss = 0.0;
        d_scan_tix = 0;
    }
    if (i < 128) d_scan_state[i] = 0ULL;
}

// ---------------- launch ----------------
extern "C" void kernel_launch(void* const* d_in, const int* in_sizes, int n_in,
                              void* d_out, int out_size) {
    const float* nfeats = (const float*)d_in[0];
    const float* efeats = (const float*)d_in[1];
    const int*   src    = (const int*)d_in[2];
    const int*   dst    = (const int*)d_in[3];
    const int*   perm   = (const int*)d_in[4];
    const float* Wm0 = (const float*)d_in[5];
    const float* bm0 = (const float*)d_in[6];
    const float* Wa0 = (const float*)d_in[7];
    const float* ba0 = (const float*)d_in[8];
    const float* Wm1 = (const float*)d_in[9];
    const float* bm1 = (const float*)d_in[10];
    const float* Wa1 = (const float*)d_in[11];
    const float* ba1 = (const float*)d_in[12];

    int n = in_sizes[0] / 64;
    int E = in_sizes[2];
    int nb = (n + 1023) / 1024;

    // created once, outside capture (first call is the non-captured correctness run)
    static cudaStream_t s2 = [] {
        cudaStream_t s; cudaStreamCreateWithFlags(&s, cudaStreamNonBlocking); return s;
    }();
    static cudaEvent_t evA = [] {
        cudaEvent_t e; cudaEventCreateWithFlags(&e, cudaEventDisableTiming); return e;
    }();
    static cudaEvent_t evB = [] {
        cudaEvent_t e; cudaEventCreateWithFlags(&e, cudaEventDisableTiming); return e;
    }();

    cudaFuncSetAttribute(k_base, cudaFuncAttributeMaxDynamicSharedMemorySize, BASE_SMEM);
    cudaFuncSetAttribute(k_l0,   cudaFuncAttributeMaxDynamicSharedMemorySize, L0_SMEM);
    cudaFuncSetAttribute(k_l1,   cudaFuncAttributeMaxDynamicSharedMemorySize, L1_SMEM);

    int gw = (n * 32 + 255) / 256;  // one warp per node
    int gl = (n + 127) / 128;       // 128 nodes per tile

    cudaEventRecord(evA, 0);                                   // fork

    k_hist   <<<(E + 255) / 256, 256>>>(dst, E);               // main chain (DRAM-bound)
    k_scan   <<<nb, 1024>>>(n, E, nb);
    k_scatter<<<(E + 255) / 256, 256>>>(src, dst, perm, E);
    k_agg3   <<<gw, 256>>>(nfeats, efeats, n);                 // 4th launch <- profiled

    cudaStreamWaitEvent(s2, evA, 0);                           // side branch (compute-bound)
    k_fold2  <<<2, 256, 0, s2>>>(Wm0, bm0, Wa0, Wm1, bm1, Wa1);
    k_base   <<<gl, 256, BASE_SMEM, s2>>>(nfeats, n);
    cudaEventRecord(evB, s2);

    cudaStreamWaitEvent(0, evB, 0);                            // join
    k_l0     <<<gl, 256, L0_SMEM>>>(ba0, n);
    k_aggh2  <<<gw, 256>>>(n);
    {
        dim3 grid(gl, 2);
        k_l1 <<<grid, 256, L1_SMEM>>>(ba1, n);
    }
    k_clean  <<<1, 128>>>((float*)d_out, (double)n * 64.0);
}